// round 11
// baseline (speedup 1.0000x reference)
#include <cuda_runtime.h>

// ---------------------------------------------------------------------------
// GAT (2-layer GATConv), N=50000, E=850000 (incl self-loops), F=128, H=4, D=32
// Branched graph:
//   stream0: gemm L1 ----------------------\
//   stream2: init -> hist -> offsets -> scatter --+--> gather L1 -> gemm L2 -> gather L2
// GEMM: W-resident (64KB smem) f32x2 GEMM, GR=64, 3 CTAs/SM (88% wave util).
// Gather: fused edge softmax + weighted feat gather, warp/node, no atomics.
// ---------------------------------------------------------------------------

#define FULL 0xffffffffu
typedef unsigned long long ull;

constexpr int NN = 50000;
constexpr int EE = 850000;
constexpr int FH = 128;   // H*D
constexpr int HH = 4;

// scratch (device globals; no allocation allowed)
__device__ float g_feat[NN * FH];
__device__ float g_hid[NN * FH];
__device__ float g_el[NN * HH];
__device__ float g_er[NN * HH];
__device__ int   g_counts[NN];
__device__ int   g_cursor[NN];
__device__ int   g_off[NN];
__device__ int   g_total;
__device__ int   g_ssrc[EE];

// ---------------------------------------------------------------------------
__device__ __forceinline__ ull pack2(float lo, float hi) {
    ull r; asm("mov.b64 %0, {%1,%2};" : "=l"(r) : "f"(lo), "f"(hi)); return r;
}
__device__ __forceinline__ float2 unpack2(ull v) {
    float2 r; asm("mov.b64 {%0,%1}, %2;" : "=f"(r.x), "=f"(r.y) : "l"(v)); return r;
}
__device__ __forceinline__ void ffma2(ull& d, ull a, ull b) {
    asm("fma.rn.f32x2 %0, %1, %2, %0;" : "+l"(d) : "l"(a), "l"(b));
}
__device__ __forceinline__ float lk(float x, float s) { return x > 0.f ? x : x * s; }
__device__ __forceinline__ unsigned s2u(const void* p) {
    unsigned a;
    asm("{ .reg .u64 t; cvta.to.shared.u64 t, %1; cvt.u32.u64 %0, t; }"
        : "=r"(a) : "l"(p));
    return a;
}
#define CPA16(d, s) asm volatile("cp.async.ca.shared.global [%0], [%1], 16;" :: "r"(d), "l"(s))
#define CPA_COMMIT() asm volatile("cp.async.commit_group;")
#define CPA_WAIT0()  asm volatile("cp.async.wait_group 0;")

// ---------------------------------------------------------------------------
__global__ void k_init() {
    int i = blockIdx.x * blockDim.x + threadIdx.x;
    if (i < NN) { g_counts[i] = 0; g_cursor[i] = 0; }
    if (i == 0) g_total = 0;
}

__global__ void k_hist(const int* __restrict__ dst) {
    int i = blockIdx.x * blockDim.x + threadIdx.x;
    if (i < EE) atomicAdd(&g_counts[dst[i]], 1);
}

// Reserve a contiguous segment per node (segments need not be node-ordered):
// block exclusive scan + one atomicAdd on g_total per block.
__global__ void k_offsets() {
    __shared__ int wsum[32];
    __shared__ int sbase;
    int i = blockIdx.x * 1024 + threadIdx.x;
    int lane = threadIdx.x & 31, warp = threadIdx.x >> 5;
    int v = (i < NN) ? g_counts[i] : 0;

    int incl = v;
#pragma unroll
    for (int o = 1; o < 32; o <<= 1) {
        int t = __shfl_up_sync(FULL, incl, o);
        if (lane >= o) incl += t;
    }
    if (lane == 31) wsum[warp] = incl;
    __syncthreads();
    if (warp == 0) {
        int w = wsum[lane];
#pragma unroll
        for (int o = 1; o < 32; o <<= 1) {
            int t = __shfl_up_sync(FULL, w, o);
            if (lane >= o) w += t;
        }
        wsum[lane] = w;
        if (lane == 31) sbase = atomicAdd(&g_total, w);
    }
    __syncthreads();
    int excl = incl - v + (warp ? wsum[warp - 1] : 0);
    if (i < NN) g_off[i] = sbase + excl;
}

__global__ void k_scatter(const int* __restrict__ src, const int* __restrict__ dst) {
    int i = blockIdx.x * blockDim.x + threadIdx.x;
    if (i < EE) {
        int v = dst[i];
        int pos = g_off[v] + atomicAdd(&g_cursor[v], 1);
        g_ssrc[pos] = src[i];
    }
}

// ---------------------------------------------------------------------------
// W-resident GEMM: feat[N,128] = X[N,128] @ W[128,128], fma.rn.f32x2.
// 256 threads / 8 warps, 64 rows/block (782 blocks, 3 CTAs/SM, 1.76 waves).
// Warp: 8 rows (4 row-pairs) x 128 cols (4 cols/lane).
//   - W: full 64KB image cp.async'd once per block into dynamic smem.
//   - X: single 32-k chunk buffer; LDG for ch+1 issued before compute(ch),
//     STS between two barriers after compute.
// smem 72.25KB/block -> 3 CTAs/SM. launch_bounds(256,3) pins regs <= 80.
// Fused el/er attention-projection epilogue.
// ---------------------------------------------------------------------------
__global__ void __launch_bounds__(256, 3) k_gemm(
        const float* __restrict__ X, const float* __restrict__ W,
        const float* __restrict__ al, const float* __restrict__ ar) {
    constexpr int GR = 64, KC = 32, NCH = FH / KC;    // 4 chunks
    constexpr int XP = GR + 2;                        // 66: bank spread
    extern __shared__ float smem[];
    float* Wsh = smem;                                // [128][128] = 64KB
    float* Xsh = smem + FH * FH;                      // [KC][XP] = 8.25KB

    int tid = threadIdx.x, lane = tid & 31, warp = tid >> 5;
    int row0 = blockIdx.x * GR;

    ull acc[4][4];
#pragma unroll
    for (int rp = 0; rp < 4; rp++)
#pragma unroll
        for (int c = 0; c < 4; c++) acc[rp][c] = 0ull;

    const float4* X4 = reinterpret_cast<const float4*>(X);

    // W: one cp.async burst, 4096 x 16B units across 256 threads
    {
        const char* gw = reinterpret_cast<const char*>(W);
        unsigned sw = s2u(Wsh);
#pragma unroll
        for (int j = 0; j < 16; j++) {
            int u = tid + 256 * j;
            CPA16(sw + u * 16, gw + u * 16);
        }
        CPA_COMMIT();
    }

    // X loader: float4 col c = tid&7 (k range 4c..4c+3), rows r = (tid>>3)+32m
    int xl_c = tid & 7, xl_rb = tid >> 3;
    float4 xreg[2];
    auto load_x = [&](int ch) {
#pragma unroll
        for (int m = 0; m < 2; m++) {
            int row = row0 + xl_rb + 32 * m;
            xreg[m] = (row < NN) ? X4[row * 32 + ch * (KC / 4) + xl_c]
                                 : make_float4(0.f, 0.f, 0.f, 0.f);
        }
    };
    auto sts_x = [&]() {
#pragma unroll
        for (int m = 0; m < 2; m++) {
            int r = xl_rb + 32 * m;
            Xsh[(4 * xl_c + 0) * XP + r] = xreg[m].x;
            Xsh[(4 * xl_c + 1) * XP + r] = xreg[m].y;
            Xsh[(4 * xl_c + 2) * XP + r] = xreg[m].z;
            Xsh[(4 * xl_c + 3) * XP + r] = xreg[m].w;
        }
    };

    // prologue: X chunk 0; wait for W
    load_x(0);
    CPA_WAIT0();          // W landed
    sts_x();
    __syncthreads();

    for (int ch = 0; ch < NCH; ch++) {
        if (ch + 1 < NCH) load_x(ch + 1);   // LDG in flight during compute

#pragma unroll 4
        for (int k = 0; k < KC; k++) {
            float4 w = *reinterpret_cast<const float4*>(
                &Wsh[(ch * KC + k) * FH + lane * 4]);
            ull w0 = pack2(w.x, w.x), w1 = pack2(w.y, w.y);
            ull w2 = pack2(w.z, w.z), w3 = pack2(w.w, w.w);
            const ull* arow = reinterpret_cast<const ull*>(&Xsh[k * XP + warp * 8]);
#pragma unroll
            for (int rp = 0; rp < 4; rp++) {
                ull a2 = arow[rp];
                ffma2(acc[rp][0], a2, w0);
                ffma2(acc[rp][1], a2, w1);
                ffma2(acc[rp][2], a2, w2);
                ffma2(acc[rp][3], a2, w3);
            }
        }

        if (ch + 1 < NCH) {
            __syncthreads();      // all readers of Xsh done
            sts_x();
            __syncthreads();      // next X visible
        }
    }

    // epilogue: store feat + fused el/er (8-lane segmented reduction per head)
    int h = lane >> 3;
    float4 alv = reinterpret_cast<const float4*>(al)[h * 8 + (lane & 7)];
    float4 arv = reinterpret_cast<const float4*>(ar)[h * 8 + (lane & 7)];
    float4* feat4 = reinterpret_cast<float4*>(g_feat);

#pragma unroll
    for (int rp = 0; rp < 4; rp++) {
        float2 c0 = unpack2(acc[rp][0]), c1 = unpack2(acc[rp][1]);
        float2 c2 = unpack2(acc[rp][2]), c3 = unpack2(acc[rp][3]);
        int rlo = row0 + warp * 8 + rp * 2;
        int rhi = rlo + 1;
        if (rlo < NN) feat4[rlo * 32 + lane] = make_float4(c0.x, c1.x, c2.x, c3.x);
        if (rhi < NN) feat4[rhi * 32 + lane] = make_float4(c0.y, c1.y, c2.y, c3.y);

        float el_lo = c0.x * alv.x + c1.x * alv.y + c2.x * alv.z + c3.x * alv.w;
        float er_lo = c0.x * arv.x + c1.x * arv.y + c2.x * arv.z + c3.x * arv.w;
        float el_hi = c0.y * alv.x + c1.y * alv.y + c2.y * alv.z + c3.y * alv.w;
        float er_hi = c0.y * arv.x + c1.y * arv.y + c2.y * arv.z + c3.y * arv.w;
#pragma unroll
        for (int o = 4; o; o >>= 1) {
            el_lo += __shfl_xor_sync(FULL, el_lo, o);
            er_lo += __shfl_xor_sync(FULL, er_lo, o);
            el_hi += __shfl_xor_sync(FULL, el_hi, o);
            er_hi += __shfl_xor_sync(FULL, er_hi, o);
        }
        if ((lane & 7) == 0) {
            if (rlo < NN) { g_el[rlo * HH + h] = el_lo; g_er[rlo * HH + h] = er_lo; }
            if (rhi < NN) { g_el[rhi * HH + h] = el_hi; g_er[rhi * HH + h] = er_hi; }
        }
    }
}

// ---------------------------------------------------------------------------
// Fused softmax + gather: one warp per dst node (no max pass; scores are O(1),
// softmax shift-invariant). Pass A: per-head denominators. Pass B: recompute
// exp, weighted float4 gather of feat[src] in registers.
// ---------------------------------------------------------------------------
__device__ __forceinline__ float4 wred_sum4(float4 v) {
#pragma unroll
    for (int o = 16; o; o >>= 1) {
        v.x += __shfl_xor_sync(FULL, v.x, o);
        v.y += __shfl_xor_sync(FULL, v.y, o);
        v.z += __shfl_xor_sync(FULL, v.z, o);
        v.w += __shfl_xor_sync(FULL, v.w, o);
    }
    return v;
}

__global__ void k_gather(const float* __restrict__ bias, float* __restrict__ out,
                         float act_slope, int apply_act) {
    int wg = (blockIdx.x * blockDim.x + threadIdx.x) >> 5;
    int lane = threadIdx.x & 31;
    if (wg >= NN) return;
    int v = wg;
    int start = g_off[v];
    int end = start + g_counts[v];

    const float4* feat4 = reinterpret_cast<const float4*>(g_feat);
    const float4* el4 = reinterpret_cast<const float4*>(g_el);
    const float* elf = g_el;

    float4 erv = reinterpret_cast<const float4*>(g_er)[v];

    float4 sm = make_float4(0.f, 0.f, 0.f, 0.f);
    for (int p = start + lane; p < end; p += 32) {
        int s = g_ssrc[p];
        float4 e = el4[s];
        sm.x += __expf(lk(e.x + erv.x, 0.2f));
        sm.y += __expf(lk(e.y + erv.y, 0.2f));
        sm.z += __expf(lk(e.z + erv.z, 0.2f));
        sm.w += __expf(lk(e.w + erv.w, 0.2f));
    }
    sm = wred_sum4(sm);

    int h = lane >> 3;
    float shd = (h == 0) ? sm.x : (h == 1) ? sm.y : (h == 2) ? sm.z : sm.w;
    float erh = (h == 0) ? erv.x : (h == 1) ? erv.y : (h == 2) ? erv.z : erv.w;
    float inv = 1.f / shd;

    float4 a0 = make_float4(0, 0, 0, 0), a1 = a0, a2 = a0, a3 = a0;
    int p = start;
#define STEP(PP, ACC)                                            \
    {                                                            \
        int s_ = g_ssrc[PP];                                     \
        float a_ = __expf(lk(elf[s_ * 4 + h] + erh, 0.2f)) * inv;\
        float4 f_ = feat4[s_ * 32 + lane];                       \
        ACC.x = fmaf(a_, f_.x, ACC.x);                           \
        ACC.y = fmaf(a_, f_.y, ACC.y);                           \
        ACC.z = fmaf(a_, f_.z, ACC.z);                           \
        ACC.w = fmaf(a_, f_.w, ACC.w);                           \
    }
    for (; p + 4 <= end; p += 4) {
        STEP(p + 0, a0); STEP(p + 1, a1); STEP(p + 2, a2); STEP(p + 3, a3);
    }
    for (; p < end; ++p) STEP(p, a0);
#undef STEP
    float4 acc;
    acc.x = (a0.x + a1.x) + (a2.x + a3.x);
    acc.y = (a0.y + a1.y) + (a2.y + a3.y);
    acc.z = (a0.z + a1.z) + (a2.z + a3.z);
    acc.w = (a0.w + a1.w) + (a2.w + a3.w);

    float4 b = reinterpret_cast<const float4*>(bias)[lane];
    acc.x += b.x; acc.y += b.y; acc.z += b.z; acc.w += b.w;
    if (apply_act) {
        acc.x = lk(acc.x, act_slope);
        acc.y = lk(acc.y, act_slope);
        acc.z = lk(acc.z, act_slope);
        acc.w = lk(acc.w, act_slope);
    }
    reinterpret_cast<float4*>(out)[v * 32 + lane] = acc;
}

// ---------------------------------------------------------------------------
extern "C" void kernel_launch(void* const* d_in, const int* in_sizes, int n_in,
                              void* d_out, int out_size) {
    const float* x   = (const float*)d_in[0];
    const int*   src = (const int*)d_in[1];
    const int*   dst = (const int*)d_in[2];
    const float* W1  = (const float*)d_in[3];
    const float* al1 = (const float*)d_in[4];
    const float* ar1 = (const float*)d_in[5];
    const float* b1  = (const float*)d_in[6];
    const float* W2  = (const float*)d_in[7];
    const float* al2 = (const float*)d_in[8];
    const float* ar2 = (const float*)d_in[9];
    const float* b2  = (const float*)d_in[10];
    float* out = (float*)d_out;

    void* p_hid = nullptr;
    cudaGetSymbolAddress(&p_hid, g_hid);
    float* hid = (float*)p_hid;

    const int GEMM_SMEM = (128 * 128 + 32 * 66) * (int)sizeof(float); // 72.25KB
    cudaFuncSetAttribute(k_gemm, cudaFuncAttributeMaxDynamicSharedMemorySize,
                         GEMM_SMEM);

    int eblocks = (EE + 255) / 256;
    int nblocks = (NN + 255) / 256;
    int gemm_blocks = (NN + 63) / 64;        // 782
    int gather_blocks = (NN + 7) / 8;        // 8 warps/block
    int off_blocks = (NN + 1023) / 1024;     // 49

    // Fork: CSR build on side stream, concurrent with gemm L1 on main stream.
    // (Stream/events are created per call and intentionally not destroyed --
    //  kernel_launch runs only a handful of times; destroying objects that
    //  participated in an active capture would invalidate the graph.)
    cudaStream_t s2;
    cudaStreamCreateWithFlags(&s2, cudaStreamNonBlocking);
    cudaEvent_t evFork, evJoin;
    cudaEventCreateWithFlags(&evFork, cudaEventDisableTiming);
    cudaEventCreateWithFlags(&evJoin, cudaEventDisableTiming);

    cudaEventRecord(evFork, 0);
    cudaStreamWaitEvent(s2, evFork, 0);

    // side stream: CSR build
    k_init<<<nblocks, 256, 0, s2>>>();
    k_hist<<<eblocks, 256, 0, s2>>>(dst);
    k_offsets<<<off_blocks, 1024, 0, s2>>>();
    k_scatter<<<eblocks, 256, 0, s2>>>(src, dst);
    cudaEventRecord(evJoin, s2);

    // main stream: gemm L1 runs concurrently with CSR build
    k_gemm<<<gemm_blocks, 256, GEMM_SMEM>>>(x, W1, al1, ar1);

    cudaStreamWaitEvent(0, evJoin, 0);   // join before gather L1
    k_gather<<<gather_blocks, 256>>>(b1, hid, 0.01f, 1);
    k_gemm<<<gemm_blocks, 256, GEMM_SMEM>>>(hid, W2, al2, ar2);
    k_gather<<<gather_blocks, 256>>>(b2, out, 0.0f, 0);
}

// round 12
// speedup vs baseline: 1.0608x; 1.0608x over previous
#include <cuda_runtime.h>

// ---------------------------------------------------------------------------
// GAT (2-layer GATConv), N=50000, E=850000 (incl self-loops), F=128, H=4, D=32
// Branched graph:
//   main:  gemm L1 ------------------------------\
//   side:  init -> hist -> offsets -> scatter ----+-> gather L1 -> gemm L2 -> gather L2
// GEMM: R10 config — W-resident (64KB smem) f32x2 GEMM, GR=128, 2 CTAs/SM,
//       X double-buffered, one barrier per chunk (measured 39.8us).
// Gather: fused edge softmax + weighted feat gather, warp/node, no atomics.
// ---------------------------------------------------------------------------

#define FULL 0xffffffffu
typedef unsigned long long ull;

constexpr int NN = 50000;
constexpr int EE = 850000;
constexpr int FH = 128;   // H*D
constexpr int HH = 4;

// scratch (device globals; no allocation allowed)
__device__ float g_feat[NN * FH];
__device__ float g_hid[NN * FH];
__device__ float g_el[NN * HH];
__device__ float g_er[NN * HH];
__device__ int   g_counts[NN];
__device__ int   g_cursor[NN];
__device__ int   g_off[NN];
__device__ int   g_total;
__device__ int   g_ssrc[EE];

// ---------------------------------------------------------------------------
__device__ __forceinline__ ull pack2(float lo, float hi) {
    ull r; asm("mov.b64 %0, {%1,%2};" : "=l"(r) : "f"(lo), "f"(hi)); return r;
}
__device__ __forceinline__ float2 unpack2(ull v) {
    float2 r; asm("mov.b64 {%0,%1}, %2;" : "=f"(r.x), "=f"(r.y) : "l"(v)); return r;
}
__device__ __forceinline__ void ffma2(ull& d, ull a, ull b) {
    asm("fma.rn.f32x2 %0, %1, %2, %0;" : "+l"(d) : "l"(a), "l"(b));
}
__device__ __forceinline__ float lk(float x, float s) { return x > 0.f ? x : x * s; }
__device__ __forceinline__ unsigned s2u(const void* p) {
    unsigned a;
    asm("{ .reg .u64 t; cvta.to.shared.u64 t, %1; cvt.u32.u64 %0, t; }"
        : "=r"(a) : "l"(p));
    return a;
}
#define CPA16(d, s) asm volatile("cp.async.ca.shared.global [%0], [%1], 16;" :: "r"(d), "l"(s))
#define CPA_COMMIT() asm volatile("cp.async.commit_group;")
#define CPA_WAIT0()  asm volatile("cp.async.wait_group 0;")

// ---------------------------------------------------------------------------
__global__ void k_init() {
    int i = blockIdx.x * blockDim.x + threadIdx.x;
    if (i < NN) { g_counts[i] = 0; g_cursor[i] = 0; }
    if (i == 0) g_total = 0;
}

__global__ void k_hist(const int* __restrict__ dst) {
    int i = blockIdx.x * blockDim.x + threadIdx.x;
    if (i < EE) atomicAdd(&g_counts[dst[i]], 1);
}

// Reserve a contiguous segment per node (segments need not be node-ordered):
// block exclusive scan + one atomicAdd on g_total per block.
__global__ void k_offsets() {
    __shared__ int wsum[32];
    __shared__ int sbase;
    int i = blockIdx.x * 1024 + threadIdx.x;
    int lane = threadIdx.x & 31, warp = threadIdx.x >> 5;
    int v = (i < NN) ? g_counts[i] : 0;

    int incl = v;
#pragma unroll
    for (int o = 1; o < 32; o <<= 1) {
        int t = __shfl_up_sync(FULL, incl, o);
        if (lane >= o) incl += t;
    }
    if (lane == 31) wsum[warp] = incl;
    __syncthreads();
    if (warp == 0) {
        int w = wsum[lane];
#pragma unroll
        for (int o = 1; o < 32; o <<= 1) {
            int t = __shfl_up_sync(FULL, w, o);
            if (lane >= o) w += t;
        }
        wsum[lane] = w;
        if (lane == 31) sbase = atomicAdd(&g_total, w);
    }
    __syncthreads();
    int excl = incl - v + (warp ? wsum[warp - 1] : 0);
    if (i < NN) g_off[i] = sbase + excl;
}

__global__ void k_scatter(const int* __restrict__ src, const int* __restrict__ dst) {
    int i = blockIdx.x * blockDim.x + threadIdx.x;
    if (i < EE) {
        int v = dst[i];
        int pos = g_off[v] + atomicAdd(&g_cursor[v], 1);
        g_ssrc[pos] = src[i];
    }
}

// ---------------------------------------------------------------------------
// W-resident pipelined GEMM (R10 config): feat = X @ W, fma.rn.f32x2.
// 256 threads / 8 warps, 128 rows/block (391 blocks, 2 CTAs/SM).
// Warp: 16 rows (8 row-pairs) x 128 cols (4 cols/lane).
//   - W: full 64KB image cp.async'd once per block into dynamic smem.
//   - X: double-buffered 32-k chunks; LDG for ch+1 before compute(ch);
//     STS into idle buffer after compute; ONE __syncthreads per chunk.
// Dynamic smem 96.5KB/block -> 2 CTAs/SM. Fused el/er epilogue.
// ---------------------------------------------------------------------------
__global__ void __launch_bounds__(256) k_gemm(
        const float* __restrict__ X, const float* __restrict__ W,
        const float* __restrict__ al, const float* __restrict__ ar) {
    constexpr int GR = 128, KC = 32, NCH = FH / KC;   // 4 chunks
    constexpr int XP = GR + 2;                        // 130: bank spread
    extern __shared__ float smem[];
    float* Wsh = smem;                                // [128][128] = 64KB
    float* Xsh = smem + FH * FH;                      // [2][KC][XP] = 33.3KB

    int tid = threadIdx.x, lane = tid & 31, warp = tid >> 5;
    int row0 = blockIdx.x * GR;

    ull acc[8][4];
#pragma unroll
    for (int rp = 0; rp < 8; rp++)
#pragma unroll
        for (int c = 0; c < 4; c++) acc[rp][c] = 0ull;

    const float4* X4 = reinterpret_cast<const float4*>(X);

    // W: one cp.async burst, 4096 x 16B units across 256 threads
    {
        const char* gw = reinterpret_cast<const char*>(W);
        unsigned sw = s2u(Wsh);
#pragma unroll
        for (int j = 0; j < 16; j++) {
            int u = tid + 256 * j;
            CPA16(sw + u * 16, gw + u * 16);
        }
        CPA_COMMIT();
    }

    // X loader mapping: float4 col c = tid&7, rows r = (tid>>3)+32m
    int xl_c = tid & 7, xl_rb = tid >> 3;
    float4 xreg[4];
    auto load_x = [&](int ch) {
#pragma unroll
        for (int m = 0; m < 4; m++) {
            int row = row0 + xl_rb + 32 * m;
            xreg[m] = (row < NN) ? X4[row * 32 + ch * (KC / 4) + xl_c]
                                 : make_float4(0.f, 0.f, 0.f, 0.f);
        }
    };
    auto sts_x = [&](int buf) {
        float* xb = Xsh + buf * (KC * XP);
#pragma unroll
        for (int m = 0; m < 4; m++) {
            int r = xl_rb + 32 * m;
            xb[(4 * xl_c + 0) * XP + r] = xreg[m].x;
            xb[(4 * xl_c + 1) * XP + r] = xreg[m].y;
            xb[(4 * xl_c + 2) * XP + r] = xreg[m].z;
            xb[(4 * xl_c + 3) * XP + r] = xreg[m].w;
        }
    };

    // prologue: X chunk 0 in buffer 0; wait W
    load_x(0);
    CPA_WAIT0();          // W landed
    sts_x(0);
    __syncthreads();

    for (int ch = 0; ch < NCH; ch++) {
        int buf = ch & 1;
        if (ch + 1 < NCH) load_x(ch + 1);   // LDG in flight during compute

        const float* xb = Xsh + buf * (KC * XP);
#pragma unroll 4
        for (int k = 0; k < KC; k++) {
            float4 w = *reinterpret_cast<const float4*>(
                &Wsh[(ch * KC + k) * FH + lane * 4]);
            ull w0 = pack2(w.x, w.x), w1 = pack2(w.y, w.y);
            ull w2 = pack2(w.z, w.z), w3 = pack2(w.w, w.w);
            const ull* arow = reinterpret_cast<const ull*>(&xb[k * XP + warp * 16]);
#pragma unroll
            for (int rp = 0; rp < 8; rp++) {
                ull a2 = arow[rp];
                ffma2(acc[rp][0], a2, w0);
                ffma2(acc[rp][1], a2, w1);
                ffma2(acc[rp][2], a2, w2);
                ffma2(acc[rp][3], a2, w3);
            }
        }

        if (ch + 1 < NCH) {
            sts_x(buf ^ 1);       // idle buffer; readers synced out last chunk
            __syncthreads();      // one barrier per chunk
        }
    }

    // epilogue: store feat + fused el/er (8-lane segmented reduction per head)
    int h = lane >> 3;
    float4 alv = reinterpret_cast<const float4*>(al)[h * 8 + (lane & 7)];
    float4 arv = reinterpret_cast<const float4*>(ar)[h * 8 + (lane & 7)];
    float4* feat4 = reinterpret_cast<float4*>(g_feat);

#pragma unroll
    for (int rp = 0; rp < 8; rp++) {
        float2 c0 = unpack2(acc[rp][0]), c1 = unpack2(acc[rp][1]);
        float2 c2 = unpack2(acc[rp][2]), c3 = unpack2(acc[rp][3]);
        int rlo = row0 + warp * 16 + rp * 2;
        int rhi = rlo + 1;
        if (rlo < NN) feat4[rlo * 32 + lane] = make_float4(c0.x, c1.x, c2.x, c3.x);
        if (rhi < NN) feat4[rhi * 32 + lane] = make_float4(c0.y, c1.y, c2.y, c3.y);

        float el_lo = c0.x * alv.x + c1.x * alv.y + c2.x * alv.z + c3.x * alv.w;
        float er_lo = c0.x * arv.x + c1.x * arv.y + c2.x * arv.z + c3.x * arv.w;
        float el_hi = c0.y * alv.x + c1.y * alv.y + c2.y * alv.z + c3.y * alv.w;
        float er_hi = c0.y * arv.x + c1.y * arv.y + c2.y * arv.z + c3.y * arv.w;
#pragma unroll
        for (int o = 4; o; o >>= 1) {
            el_lo += __shfl_xor_sync(FULL, el_lo, o);
            er_lo += __shfl_xor_sync(FULL, er_lo, o);
            el_hi += __shfl_xor_sync(FULL, el_hi, o);
            er_hi += __shfl_xor_sync(FULL, er_hi, o);
        }
        if ((lane & 7) == 0) {
            if (rlo < NN) { g_el[rlo * HH + h] = el_lo; g_er[rlo * HH + h] = er_lo; }
            if (rhi < NN) { g_el[rhi * HH + h] = el_hi; g_er[rhi * HH + h] = er_hi; }
        }
    }
}

// ---------------------------------------------------------------------------
// Fused softmax + gather: one warp per dst node (no max pass; scores are O(1),
// softmax shift-invariant). Pass A: per-head denominators. Pass B: recompute
// exp, weighted float4 gather of feat[src] in registers.
// ---------------------------------------------------------------------------
__device__ __forceinline__ float4 wred_sum4(float4 v) {
#pragma unroll
    for (int o = 16; o; o >>= 1) {
        v.x += __shfl_xor_sync(FULL, v.x, o);
        v.y += __shfl_xor_sync(FULL, v.y, o);
        v.z += __shfl_xor_sync(FULL, v.z, o);
        v.w += __shfl_xor_sync(FULL, v.w, o);
    }
    return v;
}

__global__ void k_gather(const float* __restrict__ bias, float* __restrict__ out,
                         float act_slope, int apply_act) {
    int wg = (blockIdx.x * blockDim.x + threadIdx.x) >> 5;
    int lane = threadIdx.x & 31;
    if (wg >= NN) return;
    int v = wg;
    int start = g_off[v];
    int end = start + g_counts[v];

    const float4* feat4 = reinterpret_cast<const float4*>(g_feat);
    const float4* el4 = reinterpret_cast<const float4*>(g_el);
    const float* elf = g_el;

    float4 erv = reinterpret_cast<const float4*>(g_er)[v];

    float4 sm = make_float4(0.f, 0.f, 0.f, 0.f);
    for (int p = start + lane; p < end; p += 32) {
        int s = g_ssrc[p];
        float4 e = el4[s];
        sm.x += __expf(lk(e.x + erv.x, 0.2f));
        sm.y += __expf(lk(e.y + erv.y, 0.2f));
        sm.z += __expf(lk(e.z + erv.z, 0.2f));
        sm.w += __expf(lk(e.w + erv.w, 0.2f));
    }
    sm = wred_sum4(sm);

    int h = lane >> 3;
    float shd = (h == 0) ? sm.x : (h == 1) ? sm.y : (h == 2) ? sm.z : sm.w;
    float erh = (h == 0) ? erv.x : (h == 1) ? erv.y : (h == 2) ? erv.z : erv.w;
    float inv = 1.f / shd;

    float4 a0 = make_float4(0, 0, 0, 0), a1 = a0, a2 = a0, a3 = a0;
    int p = start;
#define STEP(PP, ACC)                                            \
    {                                                            \
        int s_ = g_ssrc[PP];                                     \
        float a_ = __expf(lk(elf[s_ * 4 + h] + erh, 0.2f)) * inv;\
        float4 f_ = feat4[s_ * 32 + lane];                       \
        ACC.x = fmaf(a_, f_.x, ACC.x);                           \
        ACC.y = fmaf(a_, f_.y, ACC.y);                           \
        ACC.z = fmaf(a_, f_.z, ACC.z);                           \
        ACC.w = fmaf(a_, f_.w, ACC.w);                           \
    }
    for (; p + 4 <= end; p += 4) {
        STEP(p + 0, a0); STEP(p + 1, a1); STEP(p + 2, a2); STEP(p + 3, a3);
    }
    for (; p < end; ++p) STEP(p, a0);
#undef STEP
    float4 acc;
    acc.x = (a0.x + a1.x) + (a2.x + a3.x);
    acc.y = (a0.y + a1.y) + (a2.y + a3.y);
    acc.z = (a0.z + a1.z) + (a2.z + a3.z);
    acc.w = (a0.w + a1.w) + (a2.w + a3.w);

    float4 b = reinterpret_cast<const float4*>(bias)[lane];
    acc.x += b.x; acc.y += b.y; acc.z += b.z; acc.w += b.w;
    if (apply_act) {
        acc.x = lk(acc.x, act_slope);
        acc.y = lk(acc.y, act_slope);
        acc.z = lk(acc.z, act_slope);
        acc.w = lk(acc.w, act_slope);
    }
    reinterpret_cast<float4*>(out)[v * 32 + lane] = acc;
}

// ---------------------------------------------------------------------------
extern "C" void kernel_launch(void* const* d_in, const int* in_sizes, int n_in,
                              void* d_out, int out_size) {
    const float* x   = (const float*)d_in[0];
    const int*   src = (const int*)d_in[1];
    const int*   dst = (const int*)d_in[2];
    const float* W1  = (const float*)d_in[3];
    const float* al1 = (const float*)d_in[4];
    const float* ar1 = (const float*)d_in[5];
    const float* b1  = (const float*)d_in[6];
    const float* W2  = (const float*)d_in[7];
    const float* al2 = (const float*)d_in[8];
    const float* ar2 = (const float*)d_in[9];
    const float* b2  = (const float*)d_in[10];
    float* out = (float*)d_out;

    void* p_hid = nullptr;
    cudaGetSymbolAddress(&p_hid, g_hid);
    float* hid = (float*)p_hid;

    const int GEMM_SMEM = (128 * 128 + 2 * 32 * 130) * (int)sizeof(float); // 96.5KB
    cudaFuncSetAttribute(k_gemm, cudaFuncAttributeMaxDynamicSharedMemorySize,
                         GEMM_SMEM);

    int eblocks = (EE + 255) / 256;
    int nblocks = (NN + 255) / 256;
    int gemm_blocks = (NN + 127) / 128;      // 391
    int gather_blocks = (NN + 7) / 8;        // 8 warps/block
    int off_blocks = (NN + 1023) / 1024;     // 49

    // Fork: CSR build on side stream, concurrent with gemm L1 on main stream.
    cudaStream_t s2;
    cudaStreamCreateWithFlags(&s2, cudaStreamNonBlocking);
    cudaEvent_t evFork, evJoin;
    cudaEventCreateWithFlags(&evFork, cudaEventDisableTiming);
    cudaEventCreateWithFlags(&evJoin, cudaEventDisableTiming);

    cudaEventRecord(evFork, 0);
    cudaStreamWaitEvent(s2, evFork, 0);

    // side stream: CSR build
    k_init<<<nblocks, 256, 0, s2>>>();
    k_hist<<<eblocks, 256, 0, s2>>>(dst);
    k_offsets<<<off_blocks, 1024, 0, s2>>>();
    k_scatter<<<eblocks, 256, 0, s2>>>(src, dst);
    cudaEventRecord(evJoin, s2);

    // main stream: gemm L1 concurrent with CSR build
    k_gemm<<<gemm_blocks, 256, GEMM_SMEM>>>(x, W1, al1, ar1);

    cudaStreamWaitEvent(0, evJoin, 0);   // join before gather L1
    k_gather<<<gather_blocks, 256>>>(b1, hid, 0.01f, 1);
    k_gemm<<<gemm_blocks, 256, GEMM_SMEM>>>(hid, W2, al2, ar2);
    k_gather<<<gather_blocks, 256>>>(b2, out, 0.0f, 0);
}

// round 13
// speedup vs baseline: 1.0747x; 1.0131x over previous
#include <cuda_runtime.h>
#include <cuda_fp16.h>

// ---------------------------------------------------------------------------
// GAT (2-layer GATConv), N=50000, E=850000 (incl self-loops), F=128, H=4, D=32
// Branched graph:
//   main:  gemm L1 ------------------------------\
//   side:  init -> hist -> offsets -> scatter ----+-> gather L1 -> gemm L2 -> gather L2
// GEMM: W-resident (64KB smem) f32x2 GEMM, GR=128, 2 CTAs/SM, X double-buffered.
//       Epilogue writes feat as FP16 (halves gather read traffic) + fp32 el/er.
// Gather: fused edge softmax (fp32) + fp16-feat weighted gather, warp/node.
// ---------------------------------------------------------------------------

#define FULL 0xffffffffu
typedef unsigned long long ull;

constexpr int NN = 50000;
constexpr int EE = 850000;
constexpr int FH = 128;   // H*D
constexpr int HH = 4;

// scratch (device globals; no allocation allowed)
__device__ __half g_feat_h[NN * FH];   // fp16 projected features (gather input)
__device__ float  g_hid[NN * FH];      // layer-1 output (fp32, layer-2 GEMM in)
__device__ float  g_el[NN * HH];
__device__ float  g_er[NN * HH];
__device__ int    g_counts[NN];
__device__ int    g_cursor[NN];
__device__ int    g_off[NN];
__device__ int    g_total;
__device__ int    g_ssrc[EE];

// ---------------------------------------------------------------------------
__device__ __forceinline__ ull pack2(float lo, float hi) {
    ull r; asm("mov.b64 %0, {%1,%2};" : "=l"(r) : "f"(lo), "f"(hi)); return r;
}
__device__ __forceinline__ float2 unpack2(ull v) {
    float2 r; asm("mov.b64 {%0,%1}, %2;" : "=f"(r.x), "=f"(r.y) : "l"(v)); return r;
}
__device__ __forceinline__ void ffma2(ull& d, ull a, ull b) {
    asm("fma.rn.f32x2 %0, %1, %2, %0;" : "+l"(d) : "l"(a), "l"(b));
}
__device__ __forceinline__ float lk(float x, float s) { return x > 0.f ? x : x * s; }
__device__ __forceinline__ unsigned s2u(const void* p) {
    unsigned a;
    asm("{ .reg .u64 t; cvta.to.shared.u64 t, %1; cvt.u32.u64 %0, t; }"
        : "=r"(a) : "l"(p));
    return a;
}
#define CPA16(d, s) asm volatile("cp.async.ca.shared.global [%0], [%1], 16;" :: "r"(d), "l"(s))
#define CPA_COMMIT() asm volatile("cp.async.commit_group;")
#define CPA_WAIT0()  asm volatile("cp.async.wait_group 0;")

// ---------------------------------------------------------------------------
__global__ void k_init() {
    int i = blockIdx.x * blockDim.x + threadIdx.x;
    if (i < NN) { g_counts[i] = 0; g_cursor[i] = 0; }
    if (i == 0) g_total = 0;
}

__global__ void k_hist(const int* __restrict__ dst) {
    int i = blockIdx.x * blockDim.x + threadIdx.x;
    if (i < EE) atomicAdd(&g_counts[dst[i]], 1);
}

// Reserve a contiguous segment per node (segments need not be node-ordered):
// block exclusive scan + one atomicAdd on g_total per block.
__global__ void k_offsets() {
    __shared__ int wsum[32];
    __shared__ int sbase;
    int i = blockIdx.x * 1024 + threadIdx.x;
    int lane = threadIdx.x & 31, warp = threadIdx.x >> 5;
    int v = (i < NN) ? g_counts[i] : 0;

    int incl = v;
#pragma unroll
    for (int o = 1; o < 32; o <<= 1) {
        int t = __shfl_up_sync(FULL, incl, o);
        if (lane >= o) incl += t;
    }
    if (lane == 31) wsum[warp] = incl;
    __syncthreads();
    if (warp == 0) {
        int w = wsum[lane];
#pragma unroll
        for (int o = 1; o < 32; o <<= 1) {
            int t = __shfl_up_sync(FULL, w, o);
            if (lane >= o) w += t;
        }
        wsum[lane] = w;
        if (lane == 31) sbase = atomicAdd(&g_total, w);
    }
    __syncthreads();
    int excl = incl - v + (warp ? wsum[warp - 1] : 0);
    if (i < NN) g_off[i] = sbase + excl;
}

__global__ void k_scatter(const int* __restrict__ src, const int* __restrict__ dst) {
    int i = blockIdx.x * blockDim.x + threadIdx.x;
    if (i < EE) {
        int v = dst[i];
        int pos = g_off[v] + atomicAdd(&g_cursor[v], 1);
        g_ssrc[pos] = src[i];
    }
}

// ---------------------------------------------------------------------------
// W-resident pipelined GEMM: feat = X @ W, fma.rn.f32x2.
// 256 threads / 8 warps, 128 rows/block (391 blocks, 2 CTAs/SM).
// Warp: 16 rows (8 row-pairs) x 128 cols (4 cols/lane).
//   - W: full 64KB image cp.async'd once per block into dynamic smem.
//   - X: double-buffered 32-k chunks; LDG for ch+1 before compute(ch);
//     STS into idle buffer after compute; ONE __syncthreads per chunk.
// Epilogue: feat -> fp16 (g_feat_h), el/er from fp32 accs.
// ---------------------------------------------------------------------------
__global__ void __launch_bounds__(256) k_gemm(
        const float* __restrict__ X, const float* __restrict__ W,
        const float* __restrict__ al, const float* __restrict__ ar) {
    constexpr int GR = 128, KC = 32, NCH = FH / KC;   // 4 chunks
    constexpr int XP = GR + 2;                        // 130: bank spread
    extern __shared__ float smem[];
    float* Wsh = smem;                                // [128][128] = 64KB
    float* Xsh = smem + FH * FH;                      // [2][KC][XP] = 33.3KB

    int tid = threadIdx.x, lane = tid & 31, warp = tid >> 5;
    int row0 = blockIdx.x * GR;

    ull acc[8][4];
#pragma unroll
    for (int rp = 0; rp < 8; rp++)
#pragma unroll
        for (int c = 0; c < 4; c++) acc[rp][c] = 0ull;

    const float4* X4 = reinterpret_cast<const float4*>(X);

    // W: one cp.async burst, 4096 x 16B units across 256 threads
    {
        const char* gw = reinterpret_cast<const char*>(W);
        unsigned sw = s2u(Wsh);
#pragma unroll
        for (int j = 0; j < 16; j++) {
            int u = tid + 256 * j;
            CPA16(sw + u * 16, gw + u * 16);
        }
        CPA_COMMIT();
    }

    // X loader mapping: float4 col c = tid&7, rows r = (tid>>3)+32m
    int xl_c = tid & 7, xl_rb = tid >> 3;
    float4 xreg[4];
    auto load_x = [&](int ch) {
#pragma unroll
        for (int m = 0; m < 4; m++) {
            int row = row0 + xl_rb + 32 * m;
            xreg[m] = (row < NN) ? X4[row * 32 + ch * (KC / 4) + xl_c]
                                 : make_float4(0.f, 0.f, 0.f, 0.f);
        }
    };
    auto sts_x = [&](int buf) {
        float* xb = Xsh + buf * (KC * XP);
#pragma unroll
        for (int m = 0; m < 4; m++) {
            int r = xl_rb + 32 * m;
            xb[(4 * xl_c + 0) * XP + r] = xreg[m].x;
            xb[(4 * xl_c + 1) * XP + r] = xreg[m].y;
            xb[(4 * xl_c + 2) * XP + r] = xreg[m].z;
            xb[(4 * xl_c + 3) * XP + r] = xreg[m].w;
        }
    };

    // prologue: X chunk 0 in buffer 0; wait W
    load_x(0);
    CPA_WAIT0();          // W landed
    sts_x(0);
    __syncthreads();

    for (int ch = 0; ch < NCH; ch++) {
        int buf = ch & 1;
        if (ch + 1 < NCH) load_x(ch + 1);   // LDG in flight during compute

        const float* xb = Xsh + buf * (KC * XP);
#pragma unroll 4
        for (int k = 0; k < KC; k++) {
            float4 w = *reinterpret_cast<const float4*>(
                &Wsh[(ch * KC + k) * FH + lane * 4]);
            ull w0 = pack2(w.x, w.x), w1 = pack2(w.y, w.y);
            ull w2 = pack2(w.z, w.z), w3 = pack2(w.w, w.w);
            const ull* arow = reinterpret_cast<const ull*>(&xb[k * XP + warp * 16]);
#pragma unroll
            for (int rp = 0; rp < 8; rp++) {
                ull a2 = arow[rp];
                ffma2(acc[rp][0], a2, w0);
                ffma2(acc[rp][1], a2, w1);
                ffma2(acc[rp][2], a2, w2);
                ffma2(acc[rp][3], a2, w3);
            }
        }

        if (ch + 1 < NCH) {
            sts_x(buf ^ 1);       // idle buffer; readers synced out last chunk
            __syncthreads();      // one barrier per chunk
        }
    }

    // epilogue: fp16 feat store + fused el/er (fp32, 8-lane segmented reduce)
    int h = lane >> 3;
    float4 alv = reinterpret_cast<const float4*>(al)[h * 8 + (lane & 7)];
    float4 arv = reinterpret_cast<const float4*>(ar)[h * 8 + (lane & 7)];
    uint2* feath = reinterpret_cast<uint2*>(g_feat_h);   // 4 halves per unit

#pragma unroll
    for (int rp = 0; rp < 8; rp++) {
        float2 c0 = unpack2(acc[rp][0]), c1 = unpack2(acc[rp][1]);
        float2 c2 = unpack2(acc[rp][2]), c3 = unpack2(acc[rp][3]);
        int rlo = row0 + warp * 16 + rp * 2;
        int rhi = rlo + 1;
        if (rlo < NN) {
            __half2 a01 = __floats2half2_rn(c0.x, c1.x);
            __half2 a23 = __floats2half2_rn(c2.x, c3.x);
            feath[rlo * 32 + lane] = make_uint2(
                *reinterpret_cast<unsigned*>(&a01), *reinterpret_cast<unsigned*>(&a23));
        }
        if (rhi < NN) {
            __half2 b01 = __floats2half2_rn(c0.y, c1.y);
            __half2 b23 = __floats2half2_rn(c2.y, c3.y);
            feath[rhi * 32 + lane] = make_uint2(
                *reinterpret_cast<unsigned*>(&b01), *reinterpret_cast<unsigned*>(&b23));
        }

        float el_lo = c0.x * alv.x + c1.x * alv.y + c2.x * alv.z + c3.x * alv.w;
        float er_lo = c0.x * arv.x + c1.x * arv.y + c2.x * arv.z + c3.x * arv.w;
        float el_hi = c0.y * alv.x + c1.y * alv.y + c2.y * alv.z + c3.y * alv.w;
        float er_hi = c0.y * arv.x + c1.y * arv.y + c2.y * arv.z + c3.y * arv.w;
#pragma unroll
        for (int o = 4; o; o >>= 1) {
            el_lo += __shfl_xor_sync(FULL, el_lo, o);
            er_lo += __shfl_xor_sync(FULL, er_lo, o);
            el_hi += __shfl_xor_sync(FULL, el_hi, o);
            er_hi += __shfl_xor_sync(FULL, er_hi, o);
        }
        if ((lane & 7) == 0) {
            if (rlo < NN) { g_el[rlo * HH + h] = el_lo; g_er[rlo * HH + h] = er_lo; }
            if (rhi < NN) { g_el[rhi * HH + h] = el_hi; g_er[rhi * HH + h] = er_hi; }
        }
    }
}

// ---------------------------------------------------------------------------
// Fused softmax + gather: one warp per dst node (no max pass; scores are O(1),
// softmax shift-invariant). Pass A: per-head denominators (fp32 el/er).
// Pass B: recompute exp; weighted gather of FP16 feat rows (fp32 accumulate).
// ---------------------------------------------------------------------------
__device__ __forceinline__ float4 wred_sum4(float4 v) {
#pragma unroll
    for (int o = 16; o; o >>= 1) {
        v.x += __shfl_xor_sync(FULL, v.x, o);
        v.y += __shfl_xor_sync(FULL, v.y, o);
        v.z += __shfl_xor_sync(FULL, v.z, o);
        v.w += __shfl_xor_sync(FULL, v.w, o);
    }
    return v;
}

__global__ void k_gather(const float* __restrict__ bias, float* __restrict__ out,
                         float act_slope, int apply_act) {
    int wg = (blockIdx.x * blockDim.x + threadIdx.x) >> 5;
    int lane = threadIdx.x & 31;
    if (wg >= NN) return;
    int v = wg;
    int start = g_off[v];
    int end = start + g_counts[v];

    const uint2* feath = reinterpret_cast<const uint2*>(g_feat_h);
    const float4* el4 = reinterpret_cast<const float4*>(g_el);
    const float* elf = g_el;

    float4 erv = reinterpret_cast<const float4*>(g_er)[v];

    // pass A: per-head softmax denominators
    float4 sm = make_float4(0.f, 0.f, 0.f, 0.f);
    for (int p = start + lane; p < end; p += 32) {
        int s = g_ssrc[p];
        float4 e = el4[s];
        sm.x += __expf(lk(e.x + erv.x, 0.2f));
        sm.y += __expf(lk(e.y + erv.y, 0.2f));
        sm.z += __expf(lk(e.z + erv.z, 0.2f));
        sm.w += __expf(lk(e.w + erv.w, 0.2f));
    }
    sm = wred_sum4(sm);

    int h = lane >> 3;
    float shd = (h == 0) ? sm.x : (h == 1) ? sm.y : (h == 2) ? sm.z : sm.w;
    float erh = (h == 0) ? erv.x : (h == 1) ? erv.y : (h == 2) ? erv.z : erv.w;
    float inv = 1.f / shd;

    // pass B: weighted fp16 gather, 4-way edge unroll, fp32 accumulate
    float4 a0 = make_float4(0, 0, 0, 0), a1 = a0, a2 = a0, a3 = a0;
    int p = start;
#define STEP(PP, ACC)                                            \
    {                                                            \
        int s_ = g_ssrc[PP];                                     \
        float a_ = __expf(lk(elf[s_ * 4 + h] + erh, 0.2f)) * inv;\
        uint2 fu_ = feath[s_ * 32 + lane];                       \
        float2 f01_ = __half22float2(*reinterpret_cast<__half2*>(&fu_.x)); \
        float2 f23_ = __half22float2(*reinterpret_cast<__half2*>(&fu_.y)); \
        ACC.x = fmaf(a_, f01_.x, ACC.x);                         \
        ACC.y = fmaf(a_, f01_.y, ACC.y);                         \
        ACC.z = fmaf(a_, f23_.x, ACC.z);                         \
        ACC.w = fmaf(a_, f23_.y, ACC.w);                         \
    }
    for (; p + 4 <= end; p += 4) {
        STEP(p + 0, a0); STEP(p + 1, a1); STEP(p + 2, a2); STEP(p + 3, a3);
    }
    for (; p < end; ++p) STEP(p, a0);
#undef STEP
    float4 acc;
    acc.x = (a0.x + a1.x) + (a2.x + a3.x);
    acc.y = (a0.y + a1.y) + (a2.y + a3.y);
    acc.z = (a0.z + a1.z) + (a2.z + a3.z);
    acc.w = (a0.w + a1.w) + (a2.w + a3.w);

    float4 b = reinterpret_cast<const float4*>(bias)[lane];
    acc.x += b.x; acc.y += b.y; acc.z += b.z; acc.w += b.w;
    if (apply_act) {
        acc.x = lk(acc.x, act_slope);
        acc.y = lk(acc.y, act_slope);
        acc.z = lk(acc.z, act_slope);
        acc.w = lk(acc.w, act_slope);
    }
    reinterpret_cast<float4*>(out)[v * 32 + lane] = acc;
}

// ---------------------------------------------------------------------------
extern "C" void kernel_launch(void* const* d_in, const int* in_sizes, int n_in,
                              void* d_out, int out_size) {
    const float* x   = (const float*)d_in[0];
    const int*   src = (const int*)d_in[1];
    const int*   dst = (const int*)d_in[2];
    const float* W1  = (const float*)d_in[3];
    const float* al1 = (const float*)d_in[4];
    const float* ar1 = (const float*)d_in[5];
    const float* b1  = (const float*)d_in[6];
    const float* W2  = (const float*)d_in[7];
    const float* al2 = (const float*)d_in[8];
    const float* ar2 = (const float*)d_in[9];
    const float* b2  = (const float*)d_in[10];
    float* out = (float*)d_out;

    void* p_hid = nullptr;
    cudaGetSymbolAddress(&p_hid, g_hid);
    float* hid = (float*)p_hid;

    const int GEMM_SMEM = (128 * 128 + 2 * 32 * 130) * (int)sizeof(float); // 96.5KB
    cudaFuncSetAttribute(k_gemm, cudaFuncAttributeMaxDynamicSharedMemorySize,
                         GEMM_SMEM);

    int eblocks = (EE + 255) / 256;
    int nblocks = (NN + 255) / 256;
    int gemm_blocks = (NN + 127) / 128;      // 391
    int gather_blocks = (NN + 7) / 8;        // 8 warps/block
    int off_blocks = (NN + 1023) / 1024;     // 49

    // Fork: CSR build on side stream, concurrent with gemm L1 on main stream.
    cudaStream_t s2;
    cudaStreamCreateWithFlags(&s2, cudaStreamNonBlocking);
    cudaEvent_t evFork, evJoin;
    cudaEventCreateWithFlags(&evFork, cudaEventDisableTiming);
    cudaEventCreateWithFlags(&evJoin, cudaEventDisableTiming);

    cudaEventRecord(evFork, 0);
    cudaStreamWaitEvent(s2, evFork, 0);

    // side stream: CSR build
    k_init<<<nblocks, 256, 0, s2>>>();
    k_hist<<<eblocks, 256, 0, s2>>>(dst);
    k_offsets<<<off_blocks, 1024, 0, s2>>>();
    k_scatter<<<eblocks, 256, 0, s2>>>(src, dst);
    cudaEventRecord(evJoin, s2);

    // main stream: gemm L1 concurrent with CSR build
    k_gemm<<<gemm_blocks, 256, GEMM_SMEM>>>(x, W1, al1, ar1);

    cudaStreamWaitEvent(0, evJoin, 0);   // join before gather L1
    k_gather<<<gather_blocks, 256>>>(b1, hid, 0.01f, 1);
    k_gemm<<<gemm_blocks, 256, GEMM_SMEM>>>(hid, W2, al2, ar2);
    k_gather<<<gather_blocks, 256>>>(b2, out, 0.0f, 0);
}

// round 14
// speedup vs baseline: 1.0995x; 1.0231x over previous
#include <cuda_runtime.h>
#include <cuda_fp16.h>

// ---------------------------------------------------------------------------
// GAT (2-layer GATConv), N=50000, E=850000 (incl self-loops), F=128, H=4, D=32
// Graph (2 streams):
//   main: gemm1 ----------------------\
//   s2:   init->hist->offsets->scatter -+-> g1a -> [g1b || gemm2a(s2)] ->
//         gemm2b -> (join) -> gather2
// GEMM: W-resident (64KB smem) f32x2 GEMM, GR=128, 2 CTAs/SM, fp16 feat store.
// Gather: warp/node; pass A caches per-edge exp weights in smem; pass B
//         does LDS weight + fp16 feat gather (no recompute chain).
// ---------------------------------------------------------------------------

#define FULL 0xffffffffu
typedef unsigned long long ull;

constexpr int NN = 50000;
constexpr int EE = 850000;
constexpr int FH = 128;   // H*D
constexpr int HH = 4;
constexpr int NH = 25088; // node/row split point (196*128) for g1/gemm2 pipeline
constexpr int CAP = 128;  // cached edges per node in gather smem

// scratch (device globals; no allocation allowed)
__device__ __half g_feat_h[NN * FH];   // fp16 projected features (gather input)
__device__ float  g_hid[NN * FH];      // layer-1 output (fp32, layer-2 GEMM in)
__device__ float  g_el[NN * HH];
__device__ float  g_er[NN * HH];
__device__ int    g_counts[NN];
__device__ int    g_cursor[NN];
__device__ int    g_off[NN];
__device__ int    g_total;
__device__ int    g_ssrc[EE];

// ---------------------------------------------------------------------------
__device__ __forceinline__ ull pack2(float lo, float hi) {
    ull r; asm("mov.b64 %0, {%1,%2};" : "=l"(r) : "f"(lo), "f"(hi)); return r;
}
__device__ __forceinline__ float2 unpack2(ull v) {
    float2 r; asm("mov.b64 {%0,%1}, %2;" : "=f"(r.x), "=f"(r.y) : "l"(v)); return r;
}
__device__ __forceinline__ void ffma2(ull& d, ull a, ull b) {
    asm("fma.rn.f32x2 %0, %1, %2, %0;" : "+l"(d) : "l"(a), "l"(b));
}
__device__ __forceinline__ float lk(float x, float s) { return x > 0.f ? x : x * s; }
__device__ __forceinline__ unsigned s2u(const void* p) {
    unsigned a;
    asm("{ .reg .u64 t; cvta.to.shared.u64 t, %1; cvt.u32.u64 %0, t; }"
        : "=r"(a) : "l"(p));
    return a;
}
#define CPA16(d, s) asm volatile("cp.async.ca.shared.global [%0], [%1], 16;" :: "r"(d), "l"(s))
#define CPA_COMMIT() asm volatile("cp.async.commit_group;")
#define CPA_WAIT0()  asm volatile("cp.async.wait_group 0;")

// ---------------------------------------------------------------------------
__global__ void k_init() {
    int i = blockIdx.x * blockDim.x + threadIdx.x;
    if (i < NN) { g_counts[i] = 0; g_cursor[i] = 0; }
    if (i == 0) g_total = 0;
}

__global__ void k_hist(const int* __restrict__ dst) {
    int i = blockIdx.x * blockDim.x + threadIdx.x;
    if (i < EE) atomicAdd(&g_counts[dst[i]], 1);
}

// Reserve a contiguous segment per node (segments need not be node-ordered):
// block exclusive scan + one atomicAdd on g_total per block.
__global__ void k_offsets() {
    __shared__ int wsum[32];
    __shared__ int sbase;
    int i = blockIdx.x * 1024 + threadIdx.x;
    int lane = threadIdx.x & 31, warp = threadIdx.x >> 5;
    int v = (i < NN) ? g_counts[i] : 0;

    int incl = v;
#pragma unroll
    for (int o = 1; o < 32; o <<= 1) {
        int t = __shfl_up_sync(FULL, incl, o);
        if (lane >= o) incl += t;
    }
    if (lane == 31) wsum[warp] = incl;
    __syncthreads();
    if (warp == 0) {
        int w = wsum[lane];
#pragma unroll
        for (int o = 1; o < 32; o <<= 1) {
            int t = __shfl_up_sync(FULL, w, o);
            if (lane >= o) w += t;
        }
        wsum[lane] = w;
        if (lane == 31) sbase = atomicAdd(&g_total, w);
    }
    __syncthreads();
    int excl = incl - v + (warp ? wsum[warp - 1] : 0);
    if (i < NN) g_off[i] = sbase + excl;
}

__global__ void k_scatter(const int* __restrict__ src, const int* __restrict__ dst) {
    int i = blockIdx.x * blockDim.x + threadIdx.x;
    if (i < EE) {
        int v = dst[i];
        int pos = g_off[v] + atomicAdd(&g_cursor[v], 1);
        g_ssrc[pos] = src[i];
    }
}

// ---------------------------------------------------------------------------
// W-resident pipelined GEMM: feat = X @ W, fma.rn.f32x2.
// 256 threads / 8 warps, 128 rows/block, rows [rowbase + blk*128 ...).
// W: full 64KB cp.async once per block; X double-buffered; 1 barrier/chunk.
// Epilogue: feat -> fp16 (g_feat_h), el/er fp32.
// ---------------------------------------------------------------------------
__global__ void __launch_bounds__(256) k_gemm(
        const float* __restrict__ X, const float* __restrict__ W,
        const float* __restrict__ al, const float* __restrict__ ar,
        int rowbase) {
    constexpr int GR = 128, KC = 32, NCH = FH / KC;   // 4 chunks
    constexpr int XP = GR + 2;                        // 130: bank spread
    extern __shared__ float smem[];
    float* Wsh = smem;                                // [128][128] = 64KB
    float* Xsh = smem + FH * FH;                      // [2][KC][XP] = 33.3KB

    int tid = threadIdx.x, lane = tid & 31, warp = tid >> 5;
    int row0 = rowbase + blockIdx.x * GR;

    ull acc[8][4];
#pragma unroll
    for (int rp = 0; rp < 8; rp++)
#pragma unroll
        for (int c = 0; c < 4; c++) acc[rp][c] = 0ull;

    const float4* X4 = reinterpret_cast<const float4*>(X);

    // W: one cp.async burst, 4096 x 16B units across 256 threads
    {
        const char* gw = reinterpret_cast<const char*>(W);
        unsigned sw = s2u(Wsh);
#pragma unroll
        for (int j = 0; j < 16; j++) {
            int u = tid + 256 * j;
            CPA16(sw + u * 16, gw + u * 16);
        }
        CPA_COMMIT();
    }

    // X loader mapping: float4 col c = tid&7, rows r = (tid>>3)+32m
    int xl_c = tid & 7, xl_rb = tid >> 3;
    float4 xreg[4];
    auto load_x = [&](int ch) {
#pragma unroll
        for (int m = 0; m < 4; m++) {
            int row = row0 + xl_rb + 32 * m;
            xreg[m] = (row < NN) ? X4[row * 32 + ch * (KC / 4) + xl_c]
                                 : make_float4(0.f, 0.f, 0.f, 0.f);
        }
    };
    auto sts_x = [&](int buf) {
        float* xb = Xsh + buf * (KC * XP);
#pragma unroll
        for (int m = 0; m < 4; m++) {
            int r = xl_rb + 32 * m;
            xb[(4 * xl_c + 0) * XP + r] = xreg[m].x;
            xb[(4 * xl_c + 1) * XP + r] = xreg[m].y;
            xb[(4 * xl_c + 2) * XP + r] = xreg[m].z;
            xb[(4 * xl_c + 3) * XP + r] = xreg[m].w;
        }
    };

    load_x(0);
    CPA_WAIT0();          // W landed
    sts_x(0);
    __syncthreads();

    for (int ch = 0; ch < NCH; ch++) {
        int buf = ch & 1;
        if (ch + 1 < NCH) load_x(ch + 1);

        const float* xb = Xsh + buf * (KC * XP);
#pragma unroll 4
        for (int k = 0; k < KC; k++) {
            float4 w = *reinterpret_cast<const float4*>(
                &Wsh[(ch * KC + k) * FH + lane * 4]);
            ull w0 = pack2(w.x, w.x), w1 = pack2(w.y, w.y);
            ull w2 = pack2(w.z, w.z), w3 = pack2(w.w, w.w);
            const ull* arow = reinterpret_cast<const ull*>(&xb[k * XP + warp * 16]);
#pragma unroll
            for (int rp = 0; rp < 8; rp++) {
                ull a2 = arow[rp];
                ffma2(acc[rp][0], a2, w0);
                ffma2(acc[rp][1], a2, w1);
                ffma2(acc[rp][2], a2, w2);
                ffma2(acc[rp][3], a2, w3);
            }
        }

        if (ch + 1 < NCH) {
            sts_x(buf ^ 1);
            __syncthreads();
        }
    }

    // epilogue: fp16 feat store + fused el/er (fp32, 8-lane segmented reduce)
    int h = lane >> 3;
    float4 alv = reinterpret_cast<const float4*>(al)[h * 8 + (lane & 7)];
    float4 arv = reinterpret_cast<const float4*>(ar)[h * 8 + (lane & 7)];
    uint2* feath = reinterpret_cast<uint2*>(g_feat_h);

#pragma unroll
    for (int rp = 0; rp < 8; rp++) {
        float2 c0 = unpack2(acc[rp][0]), c1 = unpack2(acc[rp][1]);
        float2 c2 = unpack2(acc[rp][2]), c3 = unpack2(acc[rp][3]);
        int rlo = row0 + warp * 16 + rp * 2;
        int rhi = rlo + 1;
        if (rlo < NN) {
            __half2 a01 = __floats2half2_rn(c0.x, c1.x);
            __half2 a23 = __floats2half2_rn(c2.x, c3.x);
            feath[rlo * 32 + lane] = make_uint2(
                *reinterpret_cast<unsigned*>(&a01), *reinterpret_cast<unsigned*>(&a23));
        }
        if (rhi < NN) {
            __half2 b01 = __floats2half2_rn(c0.y, c1.y);
            __half2 b23 = __floats2half2_rn(c2.y, c3.y);
            feath[rhi * 32 + lane] = make_uint2(
                *reinterpret_cast<unsigned*>(&b01), *reinterpret_cast<unsigned*>(&b23));
        }

        float el_lo = c0.x * alv.x + c1.x * alv.y + c2.x * alv.z + c3.x * alv.w;
        float er_lo = c0.x * arv.x + c1.x * arv.y + c2.x * arv.z + c3.x * arv.w;
        float el_hi = c0.y * alv.x + c1.y * alv.y + c2.y * alv.z + c3.y * alv.w;
        float er_hi = c0.y * arv.x + c1.y * arv.y + c2.y * arv.z + c3.y * arv.w;
#pragma unroll
        for (int o = 4; o; o >>= 1) {
            el_lo += __shfl_xor_sync(FULL, el_lo, o);
            er_lo += __shfl_xor_sync(FULL, er_lo, o);
            el_hi += __shfl_xor_sync(FULL, el_hi, o);
            er_hi += __shfl_xor_sync(FULL, er_hi, o);
        }
        if ((lane & 7) == 0) {
            if (rlo < NN) { g_el[rlo * HH + h] = el_lo; g_er[rlo * HH + h] = er_lo; }
            if (rhi < NN) { g_el[rhi * HH + h] = el_hi; g_er[rhi * HH + h] = er_hi; }
        }
    }
}

// ---------------------------------------------------------------------------
// Fused softmax + gather over nodes [n0, n1): one warp per dst node.
// Pass A computes exp(leaky(el[src]+er[v])) per edge, caches the float4 in
// SMEM (up to CAP edges/node), accumulates per-head sums.
// Pass B: weight = cached/LDS (or recompute past CAP), fp16 feat gather,
// fp32 accumulate. No max pass (scores O(1), softmax shift-invariant).
// ---------------------------------------------------------------------------
__device__ __forceinline__ float4 wred_sum4(float4 v) {
#pragma unroll
    for (int o = 16; o; o >>= 1) {
        v.x += __shfl_xor_sync(FULL, v.x, o);
        v.y += __shfl_xor_sync(FULL, v.y, o);
        v.z += __shfl_xor_sync(FULL, v.z, o);
        v.w += __shfl_xor_sync(FULL, v.w, o);
    }
    return v;
}

__global__ void __launch_bounds__(256) k_gather(
        const float* __restrict__ bias, float* __restrict__ out,
        float act_slope, int apply_act, int n0, int n1) {
    __shared__ float wsh[8][CAP][4];   // 16KB: cached exp weights per warp
    int warp = threadIdx.x >> 5;
    int lane = threadIdx.x & 31;
    int v = n0 + (blockIdx.x * blockDim.x + threadIdx.x) / 32;
    if (v >= n1) return;
    int start = g_off[v];
    int end = start + g_counts[v];

    const uint2* feath = reinterpret_cast<const uint2*>(g_feat_h);
    const float4* el4 = reinterpret_cast<const float4*>(g_el);
    const float* elf = g_el;

    float4 erv = reinterpret_cast<const float4*>(g_er)[v];

    // pass A: exps + per-head denominators; cache exps in smem
    float4 sm = make_float4(0.f, 0.f, 0.f, 0.f);
    for (int p = start + lane; p < end; p += 32) {
        int s = g_ssrc[p];
        float4 e = el4[s];
        e.x = __expf(lk(e.x + erv.x, 0.2f));
        e.y = __expf(lk(e.y + erv.y, 0.2f));
        e.z = __expf(lk(e.z + erv.z, 0.2f));
        e.w = __expf(lk(e.w + erv.w, 0.2f));
        int i = p - start;
        if (i < CAP) *reinterpret_cast<float4*>(&wsh[warp][i][0]) = e;
        sm.x += e.x; sm.y += e.y; sm.z += e.z; sm.w += e.w;
    }
    sm = wred_sum4(sm);
    __syncwarp();

    int h = lane >> 3;
    float shd = (h == 0) ? sm.x : (h == 1) ? sm.y : (h == 2) ? sm.z : sm.w;
    float erh = (h == 0) ? erv.x : (h == 1) ? erv.y : (h == 2) ? erv.z : erv.w;
    float inv = 1.f / shd;

    // pass B: cached segment uses LDS weights; remainder recomputes
    float4 a0 = make_float4(0, 0, 0, 0), a1 = a0, a2 = a0, a3 = a0;
    int cend = (end - start > CAP) ? start + CAP : end;
    int p = start;
#define STEPC(PP, ACC)                                           \
    {                                                            \
        int s_ = g_ssrc[PP];                                     \
        float a_ = wsh[warp][(PP) - start][h] * inv;             \
        uint2 fu_ = feath[s_ * 32 + lane];                       \
        float2 f01_ = __half22float2(*reinterpret_cast<__half2*>(&fu_.x)); \
        float2 f23_ = __half22float2(*reinterpret_cast<__half2*>(&fu_.y)); \
        ACC.x = fmaf(a_, f01_.x, ACC.x);                         \
        ACC.y = fmaf(a_, f01_.y, ACC.y);                         \
        ACC.z = fmaf(a_, f23_.x, ACC.z);                         \
        ACC.w = fmaf(a_, f23_.y, ACC.w);                         \
    }
    for (; p + 4 <= cend; p += 4) {
        STEPC(p + 0, a0); STEPC(p + 1, a1); STEPC(p + 2, a2); STEPC(p + 3, a3);
    }
    for (; p < cend; ++p) STEPC(p, a0);
#undef STEPC
    // rare tail (deg > CAP): recompute weights
    for (; p < end; ++p) {
        int s_ = g_ssrc[p];
        float a_ = __expf(lk(elf[s_ * 4 + h] + erh, 0.2f)) * inv;
        uint2 fu_ = feath[s_ * 32 + lane];
        float2 f01_ = __half22float2(*reinterpret_cast<__half2*>(&fu_.x));
        float2 f23_ = __half22float2(*reinterpret_cast<__half2*>(&fu_.y));
        a0.x = fmaf(a_, f01_.x, a0.x);
        a0.y = fmaf(a_, f01_.y, a0.y);
        a0.z = fmaf(a_, f23_.x, a0.z);
        a0.w = fmaf(a_, f23_.y, a0.w);
    }
    float4 acc;
    acc.x = (a0.x + a1.x) + (a2.x + a3.x);
    acc.y = (a0.y + a1.y) + (a2.y + a3.y);
    acc.z = (a0.z + a1.z) + (a2.z + a3.z);
    acc.w = (a0.w + a1.w) + (a2.w + a3.w);

    float4 b = reinterpret_cast<const float4*>(bias)[lane];
    acc.x += b.x; acc.y += b.y; acc.z += b.z; acc.w += b.w;
    if (apply_act) {
        acc.x = lk(acc.x, act_slope);
        acc.y = lk(acc.y, act_slope);
        acc.z = lk(acc.z, act_slope);
        acc.w = lk(acc.w, act_slope);
    }
    reinterpret_cast<float4*>(out)[v * 32 + lane] = acc;
}

// ---------------------------------------------------------------------------
extern "C" void kernel_launch(void* const* d_in, const int* in_sizes, int n_in,
                              void* d_out, int out_size) {
    const float* x   = (const float*)d_in[0];
    const int*   src = (const int*)d_in[1];
    const int*   dst = (const int*)d_in[2];
    const float* W1  = (const float*)d_in[3];
    const float* al1 = (const float*)d_in[4];
    const float* ar1 = (const float*)d_in[5];
    const float* b1  = (const float*)d_in[6];
    const float* W2  = (const float*)d_in[7];
    const float* al2 = (const float*)d_in[8];
    const float* ar2 = (const float*)d_in[9];
    const float* b2  = (const float*)d_in[10];
    float* out = (float*)d_out;

    void* p_hid = nullptr;
    cudaGetSymbolAddress(&p_hid, g_hid);
    float* hid = (float*)p_hid;

    const int GEMM_SMEM = (128 * 128 + 2 * 32 * 130) * (int)sizeof(float); // 96.5KB
    cudaFuncSetAttribute(k_gemm, cudaFuncAttributeMaxDynamicSharedMemorySize,
                         GEMM_SMEM);

    int eblocks = (EE + 255) / 256;
    int nblocks = (NN + 255) / 256;
    int gemm_blocks = (NN + 127) / 128;           // 391
    int gemm_blocks_a = NH / 128;                 // 196 (rows [0,NH))
    int gemm_blocks_b = (NN - NH + 127) / 128;    // 195 (rows [NH,NN))
    int gath_blocks_a = (NH + 7) / 8;             // nodes [0,NH)
    int gath_blocks_b = (NN - NH + 7) / 8;        // nodes [NH,NN)
    int gath_blocks   = (NN + 7) / 8;
    int off_blocks = (NN + 1023) / 1024;          // 49

    cudaStream_t s2;
    cudaStreamCreateWithFlags(&s2, cudaStreamNonBlocking);
    cudaEvent_t evFork, evJoin, evG1A, ev2A;
    cudaEventCreateWithFlags(&evFork, cudaEventDisableTiming);
    cudaEventCreateWithFlags(&evJoin, cudaEventDisableTiming);
    cudaEventCreateWithFlags(&evG1A, cudaEventDisableTiming);
    cudaEventCreateWithFlags(&ev2A, cudaEventDisableTiming);

    cudaEventRecord(evFork, 0);
    cudaStreamWaitEvent(s2, evFork, 0);

    // side stream: CSR build (concurrent with gemm1)
    k_init<<<nblocks, 256, 0, s2>>>();
    k_hist<<<eblocks, 256, 0, s2>>>(dst);
    k_offsets<<<off_blocks, 1024, 0, s2>>>();
    k_scatter<<<eblocks, 256, 0, s2>>>(src, dst);
    cudaEventRecord(evJoin, s2);

    // main: gemm L1 (all rows)
    k_gemm<<<gemm_blocks, 256, GEMM_SMEM>>>(x, W1, al1, ar1, 0);

    cudaStreamWaitEvent(0, evJoin, 0);

    // gather L1 first half -> enables gemm2a on s2 while g1b runs on main
    k_gather<<<gath_blocks_a, 256>>>(b1, hid, 0.01f, 1, 0, NH);
    cudaEventRecord(evG1A, 0);

    cudaStreamWaitEvent(s2, evG1A, 0);
    k_gemm<<<gemm_blocks_a, 256, GEMM_SMEM, s2>>>(hid, W2, al2, ar2, 0);
    cudaEventRecord(ev2A, s2);

    k_gather<<<gath_blocks_b, 256>>>(b1, hid, 0.01f, 1, NH, NN);
    k_gemm<<<gemm_blocks_b, 256, GEMM_SMEM>>>(hid, W2, al2, ar2, NH);

    cudaStreamWaitEvent(0, ev2A, 0);   // need both gemm2 halves before gather2
    k_gather<<<gath_blocks, 256>>>(b2, out, 0.0f, 0, 0, NN);
}

// round 15
// speedup vs baseline: 1.1011x; 1.0015x over previous
#include <cuda_runtime.h>
#include <cuda_fp16.h>

// ---------------------------------------------------------------------------
// GAT (2-layer GATConv), N=50000, E=850000 (incl self-loops), F=128, H=4, D=32
// Graph (2 streams):
//   main: gemm1 ----------------------\
//   s2:   init->hist(+rank)->offsets->scatter -+-> g1a -> [g1b || gemm2a(s2)]
//         -> gemm2b -> (join) -> gather2
// GEMM: W-resident (64KB smem) f32x2 GEMM, GR=96 (521 blocks, 2 CTAs/SM,
//       2 even waves), fp16 feat store, fused el/er epilogue.
// CSR:  rank recorded during hist -> scatter is atomic-free.
// Gather: warp/node; pass A caches exp weights in smem; pass B LDS weight +
//         fp16 feat gather, fp32 accumulate.
// ---------------------------------------------------------------------------

#define FULL 0xffffffffu
typedef unsigned long long ull;

constexpr int NN = 50000;
constexpr int EE = 850000;
constexpr int FH = 128;   // H*D
constexpr int HH = 4;
constexpr int GR = 96;    // gemm rows/block
constexpr int NH = 25056; // node/row split (261*96) for g1/gemm2 pipeline
constexpr int CAP = 128;  // cached edges per node in gather smem

// scratch (device globals; no allocation allowed)
__device__ __half g_feat_h[NN * FH];   // fp16 projected features (gather input)
__device__ float  g_hid[NN * FH];      // layer-1 output (fp32, layer-2 GEMM in)
__device__ float  g_el[NN * HH];
__device__ float  g_er[NN * HH];
__device__ int    g_counts[NN];
__device__ int    g_off[NN];
__device__ int    g_total;
__device__ int    g_rank[EE];
__device__ int    g_ssrc[EE];

// ---------------------------------------------------------------------------
__device__ __forceinline__ ull pack2(float lo, float hi) {
    ull r; asm("mov.b64 %0, {%1,%2};" : "=l"(r) : "f"(lo), "f"(hi)); return r;
}
__device__ __forceinline__ float2 unpack2(ull v) {
    float2 r; asm("mov.b64 {%0,%1}, %2;" : "=f"(r.x), "=f"(r.y) : "l"(v)); return r;
}
__device__ __forceinline__ void ffma2(ull& d, ull a, ull b) {
    asm("fma.rn.f32x2 %0, %1, %2, %0;" : "+l"(d) : "l"(a), "l"(b));
}
__device__ __forceinline__ float lk(float x, float s) { return x > 0.f ? x : x * s; }
__device__ __forceinline__ unsigned s2u(const void* p) {
    unsigned a;
    asm("{ .reg .u64 t; cvta.to.shared.u64 t, %1; cvt.u32.u64 %0, t; }"
        : "=r"(a) : "l"(p));
    return a;
}
#define CPA16(d, s) asm volatile("cp.async.ca.shared.global [%0], [%1], 16;" :: "r"(d), "l"(s))
#define CPA_COMMIT() asm volatile("cp.async.commit_group;")
#define CPA_WAIT0()  asm volatile("cp.async.wait_group 0;")

// ---------------------------------------------------------------------------
__global__ void k_init() {
    int i = blockIdx.x * blockDim.x + threadIdx.x;
    if (i < NN) g_counts[i] = 0;
    if (i == 0) g_total = 0;
}

// histogram + per-edge rank within its dst bucket (atomic return value)
__global__ void k_hist(const int* __restrict__ dst) {
    int i = blockIdx.x * blockDim.x + threadIdx.x;
    if (i < EE) g_rank[i] = atomicAdd(&g_counts[dst[i]], 1);
}

// Reserve a contiguous segment per node (segments need not be node-ordered):
// block exclusive scan + one atomicAdd on g_total per block.
__global__ void k_offsets() {
    __shared__ int wsum[32];
    __shared__ int sbase;
    int i = blockIdx.x * 1024 + threadIdx.x;
    int lane = threadIdx.x & 31, warp = threadIdx.x >> 5;
    int v = (i < NN) ? g_counts[i] : 0;

    int incl = v;
#pragma unroll
    for (int o = 1; o < 32; o <<= 1) {
        int t = __shfl_up_sync(FULL, incl, o);
        if (lane >= o) incl += t;
    }
    if (lane == 31) wsum[warp] = incl;
    __syncthreads();
    if (warp == 0) {
        int w = wsum[lane];
#pragma unroll
        for (int o = 1; o < 32; o <<= 1) {
            int t = __shfl_up_sync(FULL, w, o);
            if (lane >= o) w += t;
        }
        wsum[lane] = w;
        if (lane == 31) sbase = atomicAdd(&g_total, w);
    }
    __syncthreads();
    int excl = incl - v + (warp ? wsum[warp - 1] : 0);
    if (i < NN) g_off[i] = sbase + excl;
}

// atomic-free scatter: position = segment base + precomputed rank
__global__ void k_scatter(const int* __restrict__ src, const int* __restrict__ dst) {
    int i = blockIdx.x * blockDim.x + threadIdx.x;
    if (i < EE) g_ssrc[g_off[dst[i]] + g_rank[i]] = src[i];
}

// ---------------------------------------------------------------------------
// W-resident pipelined GEMM: feat = X @ W, fma.rn.f32x2.
// 256 threads / 8 warps, 96 rows/block (521 blocks, 2 CTAs/SM, 2 even waves).
// Warp: 12 rows (6 row-pairs) x 128 cols (4 cols/lane).
//   - W: full 64KB image cp.async'd once per block into dynamic smem.
//   - X: double-buffered 32-k chunks; LDG for ch+1 before compute(ch);
//     STS into idle buffer after compute; ONE __syncthreads per chunk.
// smem 88.5KB/block. Epilogue: feat -> fp16 (g_feat_h), el/er fp32.
// ---------------------------------------------------------------------------
__global__ void __launch_bounds__(256) k_gemm(
        const float* __restrict__ X, const float* __restrict__ W,
        const float* __restrict__ al, const float* __restrict__ ar,
        int rowbase) {
    constexpr int KC = 32, NCH = FH / KC;             // 4 chunks
    constexpr int XP = GR + 2;                        // 98: bank spread
    extern __shared__ float smem[];
    float* Wsh = smem;                                // [128][128] = 64KB
    float* Xsh = smem + FH * FH;                      // [2][KC][XP] = 24.5KB

    int tid = threadIdx.x, lane = tid & 31, warp = tid >> 5;
    int row0 = rowbase + blockIdx.x * GR;

    ull acc[6][4];
#pragma unroll
    for (int rp = 0; rp < 6; rp++)
#pragma unroll
        for (int c = 0; c < 4; c++) acc[rp][c] = 0ull;

    const float4* X4 = reinterpret_cast<const float4*>(X);

    // W: one cp.async burst, 4096 x 16B units across 256 threads
    {
        const char* gw = reinterpret_cast<const char*>(W);
        unsigned sw = s2u(Wsh);
#pragma unroll
        for (int j = 0; j < 16; j++) {
            int u = tid + 256 * j;
            CPA16(sw + u * 16, gw + u * 16);
        }
        CPA_COMMIT();
    }

    // X loader mapping: float4 col c = tid&7, rows r = (tid>>3)+32m, m=0..2
    int xl_c = tid & 7, xl_rb = tid >> 3;
    float4 xreg[3];
    auto load_x = [&](int ch) {
#pragma unroll
        for (int m = 0; m < 3; m++) {
            int row = row0 + xl_rb + 32 * m;
            xreg[m] = (row < NN) ? X4[row * 32 + ch * (KC / 4) + xl_c]
                                 : make_float4(0.f, 0.f, 0.f, 0.f);
        }
    };
    auto sts_x = [&](int buf) {
        float* xb = Xsh + buf * (KC * XP);
#pragma unroll
        for (int m = 0; m < 3; m++) {
            int r = xl_rb + 32 * m;
            xb[(4 * xl_c + 0) * XP + r] = xreg[m].x;
            xb[(4 * xl_c + 1) * XP + r] = xreg[m].y;
            xb[(4 * xl_c + 2) * XP + r] = xreg[m].z;
            xb[(4 * xl_c + 3) * XP + r] = xreg[m].w;
        }
    };

    load_x(0);
    CPA_WAIT0();          // W landed
    sts_x(0);
    __syncthreads();

    for (int ch = 0; ch < NCH; ch++) {
        int buf = ch & 1;
        if (ch + 1 < NCH) load_x(ch + 1);

        const float* xb = Xsh + buf * (KC * XP);
#pragma unroll 4
        for (int k = 0; k < KC; k++) {
            float4 w = *reinterpret_cast<const float4*>(
                &Wsh[(ch * KC + k) * FH + lane * 4]);
            ull w0 = pack2(w.x, w.x), w1 = pack2(w.y, w.y);
            ull w2 = pack2(w.z, w.z), w3 = pack2(w.w, w.w);
            const ull* arow = reinterpret_cast<const ull*>(&xb[k * XP + warp * 12]);
#pragma unroll
            for (int rp = 0; rp < 6; rp++) {
                ull a2 = arow[rp];
                ffma2(acc[rp][0], a2, w0);
                ffma2(acc[rp][1], a2, w1);
                ffma2(acc[rp][2], a2, w2);
                ffma2(acc[rp][3], a2, w3);
            }
        }

        if (ch + 1 < NCH) {
            sts_x(buf ^ 1);
            __syncthreads();
        }
    }

    // epilogue: fp16 feat store + fused el/er (fp32, 8-lane segmented reduce)
    int h = lane >> 3;
    float4 alv = reinterpret_cast<const float4*>(al)[h * 8 + (lane & 7)];
    float4 arv = reinterpret_cast<const float4*>(ar)[h * 8 + (lane & 7)];
    uint2* feath = reinterpret_cast<uint2*>(g_feat_h);

#pragma unroll
    for (int rp = 0; rp < 6; rp++) {
        float2 c0 = unpack2(acc[rp][0]), c1 = unpack2(acc[rp][1]);
        float2 c2 = unpack2(acc[rp][2]), c3 = unpack2(acc[rp][3]);
        int rlo = row0 + warp * 12 + rp * 2;
        int rhi = rlo + 1;
        if (rlo < NN) {
            __half2 a01 = __floats2half2_rn(c0.x, c1.x);
            __half2 a23 = __floats2half2_rn(c2.x, c3.x);
            feath[rlo * 32 + lane] = make_uint2(
                *reinterpret_cast<unsigned*>(&a01), *reinterpret_cast<unsigned*>(&a23));
        }
        if (rhi < NN) {
            __half2 b01 = __floats2half2_rn(c0.y, c1.y);
            __half2 b23 = __floats2half2_rn(c2.y, c3.y);
            feath[rhi * 32 + lane] = make_uint2(
                *reinterpret_cast<unsigned*>(&b01), *reinterpret_cast<unsigned*>(&b23));
        }

        float el_lo = c0.x * alv.x + c1.x * alv.y + c2.x * alv.z + c3.x * alv.w;
        float er_lo = c0.x * arv.x + c1.x * arv.y + c2.x * arv.z + c3.x * arv.w;
        float el_hi = c0.y * alv.x + c1.y * alv.y + c2.y * alv.z + c3.y * alv.w;
        float er_hi = c0.y * arv.x + c1.y * arv.y + c2.y * arv.z + c3.y * arv.w;
#pragma unroll
        for (int o = 4; o; o >>= 1) {
            el_lo += __shfl_xor_sync(FULL, el_lo, o);
            er_lo += __shfl_xor_sync(FULL, er_lo, o);
            el_hi += __shfl_xor_sync(FULL, el_hi, o);
            er_hi += __shfl_xor_sync(FULL, er_hi, o);
        }
        if ((lane & 7) == 0) {
            if (rlo < NN) { g_el[rlo * HH + h] = el_lo; g_er[rlo * HH + h] = er_lo; }
            if (rhi < NN) { g_el[rhi * HH + h] = el_hi; g_er[rhi * HH + h] = er_hi; }
        }
    }
}

// ---------------------------------------------------------------------------
// Fused softmax + gather over nodes [n0, n1): one warp per dst node.
// Pass A: exp(leaky(el[src]+er[v])) per edge, cached in smem (<=CAP/node),
// per-head sums. Pass B: LDS weight (recompute past CAP) * fp16 feat row,
// fp32 accumulate. No max pass (scores O(1), softmax shift-invariant).
// ---------------------------------------------------------------------------
__device__ __forceinline__ float4 wred_sum4(float4 v) {
#pragma unroll
    for (int o = 16; o; o >>= 1) {
        v.x += __shfl_xor_sync(FULL, v.x, o);
        v.y += __shfl_xor_sync(FULL, v.y, o);
        v.z += __shfl_xor_sync(FULL, v.z, o);
        v.w += __shfl_xor_sync(FULL, v.w, o);
    }
    return v;
}

__global__ void __launch_bounds__(256) k_gather(
        const float* __restrict__ bias, float* __restrict__ out,
        float act_slope, int apply_act, int n0, int n1) {
    __shared__ float wsh[8][CAP][4];   // 16KB: cached exp weights per warp
    int warp = threadIdx.x >> 5;
    int lane = threadIdx.x & 31;
    int v = n0 + (blockIdx.x * blockDim.x + threadIdx.x) / 32;
    if (v >= n1) return;
    int start = g_off[v];
    int end = start + g_counts[v];

    const uint2* feath = reinterpret_cast<const uint2*>(g_feat_h);
    const float4* el4 = reinterpret_cast<const float4*>(g_el);
    const float* elf = g_el;

    float4 erv = reinterpret_cast<const float4*>(g_er)[v];

    // pass A: exps + per-head denominators; cache exps in smem
    float4 sm = make_float4(0.f, 0.f, 0.f, 0.f);
    for (int p = start + lane; p < end; p += 32) {
        int s = g_ssrc[p];
        float4 e = el4[s];
        e.x = __expf(lk(e.x + erv.x, 0.2f));
        e.y = __expf(lk(e.y + erv.y, 0.2f));
        e.z = __expf(lk(e.z + erv.z, 0.2f));
        e.w = __expf(lk(e.w + erv.w, 0.2f));
        int i = p - start;
        if (i < CAP) *reinterpret_cast<float4*>(&wsh[warp][i][0]) = e;
        sm.x += e.x; sm.y += e.y; sm.z += e.z; sm.w += e.w;
    }
    sm = wred_sum4(sm);
    __syncwarp();

    int h = lane >> 3;
    float shd = (h == 0) ? sm.x : (h == 1) ? sm.y : (h == 2) ? sm.z : sm.w;
    float erh = (h == 0) ? erv.x : (h == 1) ? erv.y : (h == 2) ? erv.z : erv.w;
    float inv = 1.f / shd;

    // pass B: cached segment uses LDS weights; remainder recomputes
    float4 a0 = make_float4(0, 0, 0, 0), a1 = a0, a2 = a0, a3 = a0;
    int cend = (end - start > CAP) ? start + CAP : end;
    int p = start;
#define STEPC(PP, ACC)                                           \
    {                                                            \
        int s_ = g_ssrc[PP];                                     \
        float a_ = wsh[warp][(PP) - start][h] * inv;             \
        uint2 fu_ = feath[s_ * 32 + lane];                       \
        float2 f01_ = __half22float2(*reinterpret_cast<__half2*>(&fu_.x)); \
        float2 f23_ = __half22float2(*reinterpret_cast<__half2*>(&fu_.y)); \
        ACC.x = fmaf(a_, f01_.x, ACC.x);                         \
        ACC.y = fmaf(a_, f01_.y, ACC.y);                         \
        ACC.z = fmaf(a_, f23_.x, ACC.z);                         \
        ACC.w = fmaf(a_, f23_.y, ACC.w);                         \
    }
    for (; p + 4 <= cend; p += 4) {
        STEPC(p + 0, a0); STEPC(p + 1, a1); STEPC(p + 2, a2); STEPC(p + 3, a3);
    }
    for (; p < cend; ++p) STEPC(p, a0);
#undef STEPC
    // rare tail (deg > CAP): recompute weights
    for (; p < end; ++p) {
        int s_ = g_ssrc[p];
        float a_ = __expf(lk(elf[s_ * 4 + h] + erh, 0.2f)) * inv;
        uint2 fu_ = feath[s_ * 32 + lane];
        float2 f01_ = __half22float2(*reinterpret_cast<__half2*>(&fu_.x));
        float2 f23_ = __half22float2(*reinterpret_cast<__half2*>(&fu_.y));
        a0.x = fmaf(a_, f01_.x, a0.x);
        a0.y = fmaf(a_, f01_.y, a0.y);
        a0.z = fmaf(a_, f23_.x, a0.z);
        a0.w = fmaf(a_, f23_.y, a0.w);
    }
    float4 acc;
    acc.x = (a0.x + a1.x) + (a2.x + a3.x);
    acc.y = (a0.y + a1.y) + (a2.y + a3.y);
    acc.z = (a0.z + a1.z) + (a2.z + a3.z);
    acc.w = (a0.w + a1.w) + (a2.w + a3.w);

    float4 b = reinterpret_cast<const float4*>(bias)[lane];
    acc.x += b.x; acc.y += b.y; acc.z += b.z; acc.w += b.w;
    if (apply_act) {
        acc.x = lk(acc.x, act_slope);
        acc.y = lk(acc.y, act_slope);
        acc.z = lk(acc.z, act_slope);
        acc.w = lk(acc.w, act_slope);
    }
    reinterpret_cast<float4*>(out)[v * 32 + lane] = acc;
}

// ---------------------------------------------------------------------------
extern "C" void kernel_launch(void* const* d_in, const int* in_sizes, int n_in,
                              void* d_out, int out_size) {
    const float* x   = (const float*)d_in[0];
    const int*   src = (const int*)d_in[1];
    const int*   dst = (const int*)d_in[2];
    const float* W1  = (const float*)d_in[3];
    const float* al1 = (const float*)d_in[4];
    const float* ar1 = (const float*)d_in[5];
    const float* b1  = (const float*)d_in[6];
    const float* W2  = (const float*)d_in[7];
    const float* al2 = (const float*)d_in[8];
    const float* ar2 = (const float*)d_in[9];
    const float* b2  = (const float*)d_in[10];
    float* out = (float*)d_out;

    void* p_hid = nullptr;
    cudaGetSymbolAddress(&p_hid, g_hid);
    float* hid = (float*)p_hid;

    const int GEMM_SMEM = (128 * 128 + 2 * 32 * (GR + 2)) * (int)sizeof(float);
    cudaFuncSetAttribute(k_gemm, cudaFuncAttributeMaxDynamicSharedMemorySize,
                         GEMM_SMEM);

    int eblocks = (EE + 255) / 256;
    int nblocks = (NN + 255) / 256;
    int gemm_blocks   = (NN + GR - 1) / GR;         // 521
    int gemm_blocks_a = NH / GR;                    // 261 (rows [0,NH))
    int gemm_blocks_b = (NN - NH + GR - 1) / GR;    // 260 (rows [NH,NN))
    int gath_blocks_a = (NH + 7) / 8;
    int gath_blocks_b = (NN - NH + 7) / 8;
    int gath_blocks   = (NN + 7) / 8;
    int off_blocks = (NN + 1023) / 1024;            // 49

    cudaStream_t s2;
    cudaStreamCreateWithFlags(&s2, cudaStreamNonBlocking);
    cudaEvent_t evFork, evJoin, evG1A, ev2A;
    cudaEventCreateWithFlags(&evFork, cudaEventDisableTiming);
    cudaEventCreateWithFlags(&evJoin, cudaEventDisableTiming);
    cudaEventCreateWithFlags(&evG1A, cudaEventDisableTiming);
    cudaEventCreateWithFlags(&ev2A, cudaEventDisableTiming);

    cudaEventRecord(evFork, 0);
    cudaStreamWaitEvent(s2, evFork, 0);

    // side stream: CSR build (concurrent with gemm1)
    k_init<<<nblocks, 256, 0, s2>>>();
    k_hist<<<eblocks, 256, 0, s2>>>(dst);
    k_offsets<<<off_blocks, 1024, 0, s2>>>();
    k_scatter<<<eblocks, 256, 0, s2>>>(src, dst);
    cudaEventRecord(evJoin, s2);

    // main: gemm L1 (all rows)
    k_gemm<<<gemm_blocks, 256, GEMM_SMEM>>>(x, W1, al1, ar1, 0);

    cudaStreamWaitEvent(0, evJoin, 0);

    // gather L1 first half -> enables gemm2a on s2 while g1b runs on main
    k_gather<<<gath_blocks_a, 256>>>(b1, hid, 0.01f, 1, 0, NH);
    cudaEventRecord(evG1A, 0);

    cudaStreamWaitEvent(s2, evG1A, 0);
    k_gemm<<<gemm_blocks_a, 256, GEMM_SMEM, s2>>>(hid, W2, al2, ar2, 0);
    cudaEventRecord(ev2A, s2);

    k_gather<<<gath_blocks_b, 256>>>(b1, hid, 0.01f, 1, NH, NN);
    k_gemm<<<gemm_blocks_b, 256, GEMM_SMEM>>>(hid, W2, al2, ar2, NH);

    cudaStreamWaitEvent(0, ev2A, 0);   // both gemm2 halves before gather2
    k_gather<<<gath_blocks, 256>>>(b2, out, 0.0f, 0, 0, NN);
}

// round 16
// speedup vs baseline: 1.1971x; 1.0872x over previous
#include <cuda_runtime.h>
#include <cuda_fp16.h>

// ---------------------------------------------------------------------------
// GAT (2-layer GATConv), N=50000, E=850000 (incl self-loops), F=128, H=4, D=32
// Graph (2 streams), 9 kernel calls:
//   s2:   hist(+rank) -> offsets(self-cleaning) -> scatter(resets total)
//   main: gemm1 (slot 4 = ncu capture) -> g1a -> [g1b || gemm2a(s2)] ->
//         gemm2b -> (join) -> gather2
// GEMM: W-resident (64KB smem) f32x2 GEMM, GR=96, fp16 feat store, fused el/er.
// Gather: SINGLE-PASS warp/node with deferred softmax normalization:
//         acc += w_e * feat[src], wsum += w_e; out = acc/wsum. No reductions,
//         no smem, half the edge sweeps of the old 2-pass version.
// ---------------------------------------------------------------------------

#define FULL 0xffffffffu
typedef unsigned long long ull;

constexpr int NN = 50000;
constexpr int EE = 850000;
constexpr int FH = 128;   // H*D
constexpr int HH = 4;
constexpr int GR = 96;    // gemm rows/block
constexpr int NH = 25056; // node/row split (261*96) for g1/gemm2 pipeline

// scratch (device globals; no allocation allowed)
__device__ __half g_feat_h[NN * FH];   // fp16 projected features (gather input)
__device__ float  g_hid[NN * FH];      // layer-1 output (fp32, layer-2 GEMM in)
__device__ float  g_el[NN * HH];
__device__ float  g_er[NN * HH];
__device__ int    g_counts[NN];        // zeroed by k_offsets each run
__device__ int    g_deg[NN];
__device__ int    g_off[NN];
__device__ int    g_total;             // reset by k_scatter each run
__device__ int    g_rank[EE];
__device__ int    g_ssrc[EE];

// ---------------------------------------------------------------------------
__device__ __forceinline__ ull pack2(float lo, float hi) {
    ull r; asm("mov.b64 %0, {%1,%2};" : "=l"(r) : "f"(lo), "f"(hi)); return r;
}
__device__ __forceinline__ float2 unpack2(ull v) {
    float2 r; asm("mov.b64 {%0,%1}, %2;" : "=f"(r.x), "=f"(r.y) : "l"(v)); return r;
}
__device__ __forceinline__ void ffma2(ull& d, ull a, ull b) {
    asm("fma.rn.f32x2 %0, %1, %2, %0;" : "+l"(d) : "l"(a), "l"(b));
}
__device__ __forceinline__ float lk(float x, float s) { return x > 0.f ? x : x * s; }
__device__ __forceinline__ unsigned s2u(const void* p) {
    unsigned a;
    asm("{ .reg .u64 t; cvta.to.shared.u64 t, %1; cvt.u32.u64 %0, t; }"
        : "=r"(a) : "l"(p));
    return a;
}
#define CPA16(d, s) asm volatile("cp.async.ca.shared.global [%0], [%1], 16;" :: "r"(d), "l"(s))
#define CPA_COMMIT() asm volatile("cp.async.commit_group;")
#define CPA_WAIT0()  asm volatile("cp.async.wait_group 0;")

// ---------------------------------------------------------------------------
// histogram + per-edge rank within its dst bucket.
// Precondition: g_counts == 0 (static init on first run; k_offsets re-zeroes).
__global__ void k_hist(const int* __restrict__ dst) {
    int i = blockIdx.x * blockDim.x + threadIdx.x;
    if (i < EE) g_rank[i] = atomicAdd(&g_counts[dst[i]], 1);
}

// Segment reservation (segments need not be node-ordered): block exclusive
// scan + one atomicAdd on g_total per block. Self-cleaning: copies counts to
// g_deg and zeroes g_counts so the next graph replay starts clean.
__global__ void k_offsets() {
    __shared__ int wsum[32];
    __shared__ int sbase;
    int i = blockIdx.x * 1024 + threadIdx.x;
    int lane = threadIdx.x & 31, warp = threadIdx.x >> 5;
    int v = 0;
    if (i < NN) { v = g_counts[i]; g_deg[i] = v; g_counts[i] = 0; }

    int incl = v;
#pragma unroll
    for (int o = 1; o < 32; o <<= 1) {
        int t = __shfl_up_sync(FULL, incl, o);
        if (lane >= o) incl += t;
    }
    if (lane == 31) wsum[warp] = incl;
    __syncthreads();
    if (warp == 0) {
        int w = wsum[lane];
#pragma unroll
        for (int o = 1; o < 32; o <<= 1) {
            int t = __shfl_up_sync(FULL, w, o);
            if (lane >= o) w += t;
        }
        wsum[lane] = w;
        if (lane == 31) sbase = atomicAdd(&g_total, w);
    }
    __syncthreads();
    int excl = incl - v + (warp ? wsum[warp - 1] : 0);
    if (i < NN) g_off[i] = sbase + excl;
}

// atomic-free scatter; also resets g_total for the next replay.
__global__ void k_scatter(const int* __restrict__ src, const int* __restrict__ dst) {
    int i = blockIdx.x * blockDim.x + threadIdx.x;
    if (i == 0) g_total = 0;
    if (i < EE) g_ssrc[g_off[dst[i]] + g_rank[i]] = src[i];
}

// ---------------------------------------------------------------------------
// W-resident pipelined GEMM: feat = X @ W, fma.rn.f32x2.
// 256 threads / 8 warps, 96 rows/block (2 CTAs/SM). Warp: 12 rows x 128 cols.
//   - W: full 64KB image cp.async'd once per block into dynamic smem.
//   - X: double-buffered 32-k chunks, LDG ahead, one barrier per chunk.
// smem 88.5KB/block. Epilogue: feat -> fp16 (g_feat_h), el/er fp32.
// ---------------------------------------------------------------------------
__global__ void __launch_bounds__(256) k_gemm(
        const float* __restrict__ X, const float* __restrict__ W,
        const float* __restrict__ al, const float* __restrict__ ar,
        int rowbase) {
    constexpr int KC = 32, NCH = FH / KC;             // 4 chunks
    constexpr int XP = GR + 2;                        // 98: bank spread
    extern __shared__ float smem[];
    float* Wsh = smem;                                // [128][128] = 64KB
    float* Xsh = smem + FH * FH;                      // [2][KC][XP] = 24.5KB

    int tid = threadIdx.x, lane = tid & 31, warp = tid >> 5;
    int row0 = rowbase + blockIdx.x * GR;

    ull acc[6][4];
#pragma unroll
    for (int rp = 0; rp < 6; rp++)
#pragma unroll
        for (int c = 0; c < 4; c++) acc[rp][c] = 0ull;

    const float4* X4 = reinterpret_cast<const float4*>(X);

    // W: one cp.async burst, 4096 x 16B units across 256 threads
    {
        const char* gw = reinterpret_cast<const char*>(W);
        unsigned sw = s2u(Wsh);
#pragma unroll
        for (int j = 0; j < 16; j++) {
            int u = tid + 256 * j;
            CPA16(sw + u * 16, gw + u * 16);
        }
        CPA_COMMIT();
    }

    int xl_c = tid & 7, xl_rb = tid >> 3;
    float4 xreg[3];
    auto load_x = [&](int ch) {
#pragma unroll
        for (int m = 0; m < 3; m++) {
            int row = row0 + xl_rb + 32 * m;
            xreg[m] = (row < NN) ? X4[row * 32 + ch * (KC / 4) + xl_c]
                                 : make_float4(0.f, 0.f, 0.f, 0.f);
        }
    };
    auto sts_x = [&](int buf) {
        float* xb = Xsh + buf * (KC * XP);
#pragma unroll
        for (int m = 0; m < 3; m++) {
            int r = xl_rb + 32 * m;
            xb[(4 * xl_c + 0) * XP + r] = xreg[m].x;
            xb[(4 * xl_c + 1) * XP + r] = xreg[m].y;
            xb[(4 * xl_c + 2) * XP + r] = xreg[m].z;
            xb[(4 * xl_c + 3) * XP + r] = xreg[m].w;
        }
    };

    load_x(0);
    CPA_WAIT0();          // W landed
    sts_x(0);
    __syncthreads();

    for (int ch = 0; ch < NCH; ch++) {
        int buf = ch & 1;
        if (ch + 1 < NCH) load_x(ch + 1);

        const float* xb = Xsh + buf * (KC * XP);
#pragma unroll 4
        for (int k = 0; k < KC; k++) {
            float4 w = *reinterpret_cast<const float4*>(
                &Wsh[(ch * KC + k) * FH + lane * 4]);
            ull w0 = pack2(w.x, w.x), w1 = pack2(w.y, w.y);
            ull w2 = pack2(w.z, w.z), w3 = pack2(w.w, w.w);
            const ull* arow = reinterpret_cast<const ull*>(&xb[k * XP + warp * 12]);
#pragma unroll
            for (int rp = 0; rp < 6; rp++) {
                ull a2 = arow[rp];
                ffma2(acc[rp][0], a2, w0);
                ffma2(acc[rp][1], a2, w1);
                ffma2(acc[rp][2], a2, w2);
                ffma2(acc[rp][3], a2, w3);
            }
        }

        if (ch + 1 < NCH) {
            sts_x(buf ^ 1);
            __syncthreads();
        }
    }

    // epilogue: fp16 feat store + fused el/er (fp32, 8-lane segmented reduce)
    int h = lane >> 3;
    float4 alv = reinterpret_cast<const float4*>(al)[h * 8 + (lane & 7)];
    float4 arv = reinterpret_cast<const float4*>(ar)[h * 8 + (lane & 7)];
    uint2* feath = reinterpret_cast<uint2*>(g_feat_h);

#pragma unroll
    for (int rp = 0; rp < 6; rp++) {
        float2 c0 = unpack2(acc[rp][0]), c1 = unpack2(acc[rp][1]);
        float2 c2 = unpack2(acc[rp][2]), c3 = unpack2(acc[rp][3]);
        int rlo = row0 + warp * 12 + rp * 2;
        int rhi = rlo + 1;
        if (rlo < NN) {
            __half2 a01 = __floats2half2_rn(c0.x, c1.x);
            __half2 a23 = __floats2half2_rn(c2.x, c3.x);
            feath[rlo * 32 + lane] = make_uint2(
                *reinterpret_cast<unsigned*>(&a01), *reinterpret_cast<unsigned*>(&a23));
        }
        if (rhi < NN) {
            __half2 b01 = __floats2half2_rn(c0.y, c1.y);
            __half2 b23 = __floats2half2_rn(c2.y, c3.y);
            feath[rhi * 32 + lane] = make_uint2(
                *reinterpret_cast<unsigned*>(&b01), *reinterpret_cast<unsigned*>(&b23));
        }

        float el_lo = c0.x * alv.x + c1.x * alv.y + c2.x * alv.z + c3.x * alv.w;
        float er_lo = c0.x * arv.x + c1.x * arv.y + c2.x * arv.z + c3.x * arv.w;
        float el_hi = c0.y * alv.x + c1.y * alv.y + c2.y * alv.z + c3.y * alv.w;
        float er_hi = c0.y * arv.x + c1.y * arv.y + c2.y * arv.z + c3.y * arv.w;
#pragma unroll
        for (int o = 4; o; o >>= 1) {
            el_lo += __shfl_xor_sync(FULL, el_lo, o);
            er_lo += __shfl_xor_sync(FULL, er_lo, o);
            el_hi += __shfl_xor_sync(FULL, el_hi, o);
            er_hi += __shfl_xor_sync(FULL, er_hi, o);
        }
        if ((lane & 7) == 0) {
            if (rlo < NN) { g_el[rlo * HH + h] = el_lo; g_er[rlo * HH + h] = er_lo; }
            if (rhi < NN) { g_el[rhi * HH + h] = el_hi; g_er[rhi * HH + h] = er_hi; }
        }
    }
}

// ---------------------------------------------------------------------------
// SINGLE-PASS fused softmax+gather over nodes [n0, n1): one warp per node.
// Deferred normalization: every lane walks all edges of its node, computing
// w_e = exp(leaky(el[src][h] + er[v][h])) for its own head only, accumulating
// acc += w_e * feat16[src] and wsum += w_e. Final: out = acc/wsum + bias.
// No warp reductions, no smem, one edge sweep.
// ---------------------------------------------------------------------------
__global__ void __launch_bounds__(256) k_gather(
        const float* __restrict__ bias, float* __restrict__ out,
        float act_slope, int apply_act, int n0, int n1) {
    int lane = threadIdx.x & 31;
    int v = n0 + (blockIdx.x * blockDim.x + threadIdx.x) / 32;
    if (v >= n1) return;
    int start = g_off[v];
    int end = start + g_deg[v];

    const uint2* feath = reinterpret_cast<const uint2*>(g_feat_h);
    const float* elf = g_el;

    int h = lane >> 3;
    float erh = g_er[v * HH + h];

    float4 a0 = make_float4(0, 0, 0, 0), a1 = a0, a2 = a0, a3 = a0;
    float ws0 = 0.f, ws1 = 0.f, ws2 = 0.f, ws3 = 0.f;
    int p = start;
#define STEP(PP, ACC, WS)                                        \
    {                                                            \
        int s_ = g_ssrc[PP];                                     \
        float w_ = __expf(lk(elf[s_ * 4 + h] + erh, 0.2f));      \
        uint2 fu_ = feath[s_ * 32 + lane];                       \
        float2 f01_ = __half22float2(*reinterpret_cast<__half2*>(&fu_.x)); \
        float2 f23_ = __half22float2(*reinterpret_cast<__half2*>(&fu_.y)); \
        ACC.x = fmaf(w_, f01_.x, ACC.x);                         \
        ACC.y = fmaf(w_, f01_.y, ACC.y);                         \
        ACC.z = fmaf(w_, f23_.x, ACC.z);                         \
        ACC.w = fmaf(w_, f23_.y, ACC.w);                         \
        WS += w_;                                                \
    }
    for (; p + 4 <= end; p += 4) {
        STEP(p + 0, a0, ws0); STEP(p + 1, a1, ws1);
        STEP(p + 2, a2, ws2); STEP(p + 3, a3, ws3);
    }
    for (; p < end; ++p) STEP(p, a0, ws0);
#undef STEP
    float4 acc;
    acc.x = (a0.x + a1.x) + (a2.x + a3.x);
    acc.y = (a0.y + a1.y) + (a2.y + a3.y);
    acc.z = (a0.z + a1.z) + (a2.z + a3.z);
    acc.w = (a0.w + a1.w) + (a2.w + a3.w);
    float inv = 1.f / ((ws0 + ws1) + (ws2 + ws3));

    float4 b = reinterpret_cast<const float4*>(bias)[lane];
    acc.x = fmaf(acc.x, inv, b.x);
    acc.y = fmaf(acc.y, inv, b.y);
    acc.z = fmaf(acc.z, inv, b.z);
    acc.w = fmaf(acc.w, inv, b.w);
    if (apply_act) {
        acc.x = lk(acc.x, act_slope);
        acc.y = lk(acc.y, act_slope);
        acc.z = lk(acc.z, act_slope);
        acc.w = lk(acc.w, act_slope);
    }
    reinterpret_cast<float4*>(out)[v * 32 + lane] = acc;
}

// ---------------------------------------------------------------------------
extern "C" void kernel_launch(void* const* d_in, const int* in_sizes, int n_in,
                              void* d_out, int out_size) {
    const float* x   = (const float*)d_in[0];
    const int*   src = (const int*)d_in[1];
    const int*   dst = (const int*)d_in[2];
    const float* W1  = (const float*)d_in[3];
    const float* al1 = (const float*)d_in[4];
    const float* ar1 = (const float*)d_in[5];
    const float* b1  = (const float*)d_in[6];
    const float* W2  = (const float*)d_in[7];
    const float* al2 = (const float*)d_in[8];
    const float* ar2 = (const float*)d_in[9];
    const float* b2  = (const float*)d_in[10];
    float* out = (float*)d_out;

    void* p_hid = nullptr;
    cudaGetSymbolAddress(&p_hid, g_hid);
    float* hid = (float*)p_hid;

    const int GEMM_SMEM = (128 * 128 + 2 * 32 * (GR + 2)) * (int)sizeof(float);
    cudaFuncSetAttribute(k_gemm, cudaFuncAttributeMaxDynamicSharedMemorySize,
                         GEMM_SMEM);

    int eblocks = (EE + 255) / 256;
    int gemm_blocks   = (NN + GR - 1) / GR;         // 521
    int gemm_blocks_a = NH / GR;                    // 261 (rows [0,NH))
    int gemm_blocks_b = (NN - NH + GR - 1) / GR;    // 260 (rows [NH,NN))
    int gath_blocks_a = (NH + 7) / 8;
    int gath_blocks_b = (NN - NH + 7) / 8;
    int gath_blocks   = (NN + 7) / 8;
    int off_blocks = (NN + 1023) / 1024;            // 49

    cudaStream_t s2;
    cudaStreamCreateWithFlags(&s2, cudaStreamNonBlocking);
    cudaEvent_t evFork, evJoin, evG1A, ev2A;
    cudaEventCreateWithFlags(&evFork, cudaEventDisableTiming);
    cudaEventCreateWithFlags(&evJoin, cudaEventDisableTiming);
    cudaEventCreateWithFlags(&evG1A, cudaEventDisableTiming);
    cudaEventCreateWithFlags(&ev2A, cudaEventDisableTiming);

    cudaEventRecord(evFork, 0);
    cudaStreamWaitEvent(s2, evFork, 0);

    // side stream: CSR build (concurrent with gemm1); self-cleaning
    k_hist<<<eblocks, 256, 0, s2>>>(dst);                      // call 1
    k_offsets<<<off_blocks, 1024, 0, s2>>>();                  // call 2
    k_scatter<<<eblocks, 256, 0, s2>>>(src, dst);              // call 3
    cudaEventRecord(evJoin, s2);

    // main: gemm L1 (all rows) — 4th launch call = ncu capture slot
    k_gemm<<<gemm_blocks, 256, GEMM_SMEM>>>(x, W1, al1, ar1, 0);

    cudaStreamWaitEvent(0, evJoin, 0);

    // gather L1 first half -> enables gemm2a on s2 while g1b runs on main
    k_gather<<<gath_blocks_a, 256>>>(b1, hid, 0.01f, 1, 0, NH);
    cudaEventRecord(evG1A, 0);

    cudaStreamWaitEvent(s2, evG1A, 0);
    k_gemm<<<gemm_blocks_a, 256, GEMM_SMEM, s2>>>(hid, W2, al2, ar2, 0);
    cudaEventRecord(ev2A, s2);

    k_gather<<<gath_blocks_b, 256>>>(b1, hid, 0.01f, 1, NH, NN);
    k_gemm<<<gemm_blocks_b, 256, GEMM_SMEM>>>(hid, W2, al2, ar2, NH);

    cudaStreamWaitEvent(0, ev2A, 0);   // both gemm2 halves before gather2
    k_gather<<<gath_blocks, 256>>>(b2, out, 0.0f, 0, 0, NN);
}